// round 1
// baseline (speedup 1.0000x reference)
#include <cuda_runtime.h>

// Shapes (fixed by the problem)
//   Q: [2, 2048, 1024]  mask: [2, 2048]  W_*: [1024, 1024]  b_*: [1024]
//   out: [2, 2048, 1024] fp32
// Scratch (device globals; no allocation in kernel_launch):
//   g_qT, g_kT : [b*16+h][64(dk)][2048(s)]  (transposed for attention)
//   g_v        : [b*16+h][2048(s)][64(dv)]

__device__ float g_qT[2 * 16 * 64 * 2048];
__device__ float g_kT[2 * 16 * 64 * 2048];
__device__ float g_v [2 * 16 * 2048 * 64];

// ---------------------------------------------------------------------------
// Fused QKV projection: C[m,n] = sum_k A[m,k] * W[n,k] + bias[n]
// m = b*2048+s (4096), n = h*64+d (1024), k = 0..1023.
// blockIdx.z selects projection {Q,K,V}. 64x64 tile, BK=16, 256 threads, 4x4/thread.
// ---------------------------------------------------------------------------
__global__ __launch_bounds__(256)
void proj_kernel(const float* __restrict__ A,
                 const float* __restrict__ Wq, const float* __restrict__ bq,
                 const float* __restrict__ Wk, const float* __restrict__ bk,
                 const float* __restrict__ Wv, const float* __restrict__ bv)
{
    __shared__ float As[16][68];   // As[k][m], padded
    __shared__ float Bs[16][68];   // Bs[k][n], padded

    const int proj = blockIdx.z;
    const float* W    = (proj == 0) ? Wq : (proj == 1) ? Wk : Wv;
    const float* bias = (proj == 0) ? bq : (proj == 1) ? bk : bv;

    const int tid = threadIdx.x;
    const int tx  = tid & 15;      // n sub-tile
    const int ty  = tid >> 4;      // m sub-tile
    const int m0  = blockIdx.y << 6;
    const int n0  = blockIdx.x << 6;

    // tile-load mapping: 64 rows x 4 float4
    const int lr  = tid >> 2;            // 0..63 (row within tile)
    const int lk4 = (tid & 3) << 2;      // 0,4,8,12 (k within tile)

    const float* Aptr = A + (m0 + lr) * 1024 + lk4;
    const float* Wptr = W + (n0 + lr) * 1024 + lk4;

    float c[4][4] = {};

    for (int kt = 0; kt < 64; kt++) {
        const float4 av = *(const float4*)(Aptr + kt * 16);
        const float4 wv = *(const float4*)(Wptr + kt * 16);
        __syncthreads();
        As[lk4 + 0][lr] = av.x; As[lk4 + 1][lr] = av.y;
        As[lk4 + 2][lr] = av.z; As[lk4 + 3][lr] = av.w;
        Bs[lk4 + 0][lr] = wv.x; Bs[lk4 + 1][lr] = wv.y;
        Bs[lk4 + 2][lr] = wv.z; Bs[lk4 + 3][lr] = wv.w;
        __syncthreads();

        #pragma unroll
        for (int kk = 0; kk < 16; kk++) {
            const float4 a4 = *(const float4*)&As[kk][ty << 2];
            const float4 b4 = *(const float4*)&Bs[kk][tx << 2];
            float a_[4] = {a4.x, a4.y, a4.z, a4.w};
            float b_[4] = {b4.x, b4.y, b4.z, b4.w};
            #pragma unroll
            for (int i = 0; i < 4; i++)
                #pragma unroll
                for (int j = 0; j < 4; j++)
                    c[i][j] += a_[i] * b_[j];
        }
    }

    const float4 bv4 = *(const float4*)(bias + n0 + (tx << 2));
    const float bb[4] = {bv4.x, bv4.y, bv4.z, bv4.w};

    const int b      = m0 >> 11;            // batch (tile never crosses batch: 2048 % 64 == 0)
    const int s_base = (m0 & 2047) + (ty << 2);
    const int h      = n0 >> 6;              // whole block is one head (BN == 64)
    const int bh     = b * 16 + h;

    if (proj < 2) {
        // transposed store: [bh][dk][s], 4 consecutive s per float4
        float* dst = (proj == 0) ? g_qT : g_kT;
        #pragma unroll
        for (int j = 0; j < 4; j++) {
            const int dk = (tx << 2) + j;
            float4 o = make_float4(c[0][j] + bb[j], c[1][j] + bb[j],
                                   c[2][j] + bb[j], c[3][j] + bb[j]);
            *(float4*)&dst[(size_t)(bh * 64 + dk) * 2048 + s_base] = o;
        }
    } else {
        // natural store: [bh][s][dv]
        #pragma unroll
        for (int i = 0; i < 4; i++) {
            float4 o = make_float4(c[i][0] + bb[0], c[i][1] + bb[1],
                                   c[i][2] + bb[2], c[i][3] + bb[3]);
            *(float4*)&g_v[(size_t)(bh * 2048 + s_base + i) * 64 + (tx << 2)] = o;
        }
    }
}

// ---------------------------------------------------------------------------
// Attention: per (bh, 64-query tile) block, stream 64-key tiles.
//   S[q,k] = sum_dk Qs[dk][q]*Ks[dk][k] * (1/8);  P = exp(S)*mask[k]
//   acc[q,dv] += P @ V;  dsum[q] += sum_k P;  out = acc/(dsum+1e-8)
// 256 threads; S-phase thread owns q=4ty.. x k=4tx..; PV-phase q=4ty.. x dv=4tx..
// ---------------------------------------------------------------------------
#define ATTN_SMEM_FLOATS (4 * 64 * 68 + 64)

__global__ __launch_bounds__(256)
void attn_kernel(const float* __restrict__ mask, float* __restrict__ out)
{
    extern __shared__ float sm[];
    float* Qs    = sm;               // [64(dk)][68] cols = q
    float* Ks    = Qs + 64 * 68;     // [64(dk)][68] cols = key
    float* Vs    = Ks + 64 * 68;     // [64(key)][68] cols = dv
    float* Ps    = Vs + 64 * 68;     // [64(q)][68]  cols = key
    float* maskS = Ps + 64 * 68;     // [64]

    const int tid = threadIdx.x;
    const int tx  = tid & 15;
    const int ty  = tid >> 4;
    const int q0  = blockIdx.x << 6;
    const int bh  = blockIdx.y;
    const int b   = bh >> 4;
    const int h   = bh & 15;

    // Load Q tile once: already [dk][s] in gmem -> straight float4 copy
    #pragma unroll
    for (int r = 0; r < 4; r++) {
        const int idx = tid + (r << 8);
        const int row = idx >> 4;
        const int c4  = (idx & 15) << 2;
        *(float4*)&Qs[row * 68 + c4] =
            *(const float4*)&g_qT[(size_t)(bh * 64 + row) * 2048 + q0 + c4];
    }

    float acc[4][4] = {};
    float dsum[4]   = {};

    for (int kt = 0; kt < 32; kt++) {
        const int k0 = kt << 6;
        __syncthreads();   // previous PV done before overwriting Ks/Vs/Ps
        #pragma unroll
        for (int r = 0; r < 4; r++) {
            const int idx = tid + (r << 8);
            const int row = idx >> 4;
            const int c4  = (idx & 15) << 2;
            *(float4*)&Ks[row * 68 + c4] =
                *(const float4*)&g_kT[(size_t)(bh * 64 + row) * 2048 + k0 + c4];
            *(float4*)&Vs[row * 68 + c4] =
                *(const float4*)&g_v[(size_t)(bh * 2048 + k0 + row) * 64 + c4];
        }
        if (tid < 64) maskS[tid] = mask[b * 2048 + k0 + tid];
        __syncthreads();

        // ---- S = Q^T K (64x64, 4x4 per thread) ----
        float s[4][4] = {};
        #pragma unroll 8
        for (int kk = 0; kk < 64; kk++) {
            const float4 a4 = *(const float4*)&Qs[kk * 68 + (ty << 2)];
            const float4 b4 = *(const float4*)&Ks[kk * 68 + (tx << 2)];
            float a_[4] = {a4.x, a4.y, a4.z, a4.w};
            float b_[4] = {b4.x, b4.y, b4.z, b4.w};
            #pragma unroll
            for (int i = 0; i < 4; i++)
                #pragma unroll
                for (int j = 0; j < 4; j++)
                    s[i][j] += a_[i] * b_[j];
        }

        // ---- P = exp(S/8) * mask; row-sum; stage P to SMEM ----
        float mloc[4];
        #pragma unroll
        for (int j = 0; j < 4; j++) mloc[j] = maskS[(tx << 2) + j];
        #pragma unroll
        for (int i = 0; i < 4; i++) {
            #pragma unroll
            for (int j = 0; j < 4; j++) {
                const float p = __expf(s[i][j] * 0.125f) * mloc[j];
                s[i][j] = p;
                dsum[i] += p;
            }
            *(float4*)&Ps[((ty << 2) + i) * 68 + (tx << 2)] =
                make_float4(s[i][0], s[i][1], s[i][2], s[i][3]);
        }
        __syncthreads();

        // ---- acc += P @ V ----
        #pragma unroll 8
        for (int kk = 0; kk < 64; kk++) {
            float pa[4];
            #pragma unroll
            for (int i = 0; i < 4; i++)
                pa[i] = Ps[((ty << 2) + i) * 68 + kk];
            const float4 v4 = *(const float4*)&Vs[kk * 68 + (tx << 2)];
            float v_[4] = {v4.x, v4.y, v4.z, v4.w};
            #pragma unroll
            for (int i = 0; i < 4; i++)
                #pragma unroll
                for (int j = 0; j < 4; j++)
                    acc[i][j] += pa[i] * v_[j];
        }
    }

    // reduce dsum across the 16 tx lanes (lanes 0-15 / 16-31 are separate ty rows)
    #pragma unroll
    for (int i = 0; i < 4; i++) {
        float d = dsum[i];
        d += __shfl_xor_sync(0xffffffffu, d, 8);
        d += __shfl_xor_sync(0xffffffffu, d, 4);
        d += __shfl_xor_sync(0xffffffffu, d, 2);
        d += __shfl_xor_sync(0xffffffffu, d, 1);
        dsum[i] = 1.0f / (d + 1e-8f);
    }

    // out: [b, s, h*64 + dv]
    #pragma unroll
    for (int i = 0; i < 4; i++) {
        const int q = q0 + (ty << 2) + i;
        float4 o = make_float4(acc[i][0] * dsum[i], acc[i][1] * dsum[i],
                               acc[i][2] * dsum[i], acc[i][3] * dsum[i]);
        *(float4*)&out[(size_t)((b * 2048 + q) * 16 + h) * 64 + (tx << 2)] = o;
    }
}

// ---------------------------------------------------------------------------
extern "C" void kernel_launch(void* const* d_in, const int* in_sizes, int n_in,
                              void* d_out, int out_size)
{
    const float* Q    = (const float*)d_in[0];
    const float* mask = (const float*)d_in[1];
    const float* Wq   = (const float*)d_in[2];
    const float* bq   = (const float*)d_in[3];
    const float* Wk   = (const float*)d_in[4];
    const float* bk   = (const float*)d_in[5];
    const float* Wv   = (const float*)d_in[6];
    const float* bv   = (const float*)d_in[7];
    float* out = (float*)d_out;

    cudaFuncSetAttribute(attn_kernel,
                         cudaFuncAttributeMaxDynamicSharedMemorySize,
                         ATTN_SMEM_FLOATS * (int)sizeof(float));

    proj_kernel<<<dim3(16, 64, 3), 256>>>(Q, Wq, bq, Wk, bk, Wv, bv);
    attn_kernel<<<dim3(32, 32), 256, ATTN_SMEM_FLOATS * sizeof(float)>>>(mask, out);
}

// round 3
// speedup vs baseline: 1.8633x; 1.8633x over previous
#include <cuda_runtime.h>
#include <cstdint>

// Shapes: Q[2,2048,1024], mask[2,2048], W_*[1024,1024], b_*[1024], out[2,2048,1024] fp32
// Scratch layouts (natural for mma.sync row.col fragments):
//   g_q, g_k : [bh][s][64]      (A row-major / B col-major for QK^T)
//   g_vT     : [bh][64(dv)][2048(s)]  (B col-major for P@V)
__device__ float g_q [2 * 16 * 2048 * 64];
__device__ float g_k [2 * 16 * 2048 * 64];
__device__ float g_vT[2 * 16 * 64 * 2048];

// ---------------------------------------------------------------------------
// helpers
// ---------------------------------------------------------------------------
__device__ __forceinline__ float tf32r(float x) {
    uint32_t u;
    asm("cvt.rna.tf32.f32 %0, %1;" : "=r"(u) : "f"(x));
    return __uint_as_float(u);
}
__device__ __forceinline__ uint32_t fu(float x) { return __float_as_uint(x); }

// D += A(m16k8,row) * B(k8n8,col)   tf32 inputs, f32 accum
__device__ __forceinline__ void mma8(float* c, const uint32_t* a, const uint32_t* b) {
    asm volatile(
        "mma.sync.aligned.m16n8k8.row.col.f32.tf32.tf32.f32 "
        "{%0,%1,%2,%3}, {%4,%5,%6,%7}, {%8,%9}, {%0,%1,%2,%3};"
        : "+f"(c[0]), "+f"(c[1]), "+f"(c[2]), "+f"(c[3])
        : "r"(a[0]), "r"(a[1]), "r"(a[2]), "r"(a[3]), "r"(b[0]), "r"(b[1]));
}

// ---------------------------------------------------------------------------
// Projection GEMM (tf32 mma): C[m,n] = sum_k A[m,k]*W[n,k] + bias[n]
// m = b*2048+s (4096), n = h*64+d (1024).
// Block: 256 thr (8 warps, 4m x 2n), tile M=128 N=64, K-chunk 32.
// grid = (16 n-tiles, 32 m-tiles, 3 proj)
// ---------------------------------------------------------------------------
__global__ __launch_bounds__(256)
void proj_kernel(const float* __restrict__ A,
                 const float* __restrict__ Wq, const float* __restrict__ bq,
                 const float* __restrict__ Wk, const float* __restrict__ bk,
                 const float* __restrict__ Wv, const float* __restrict__ bv)
{
    __shared__ float As[128][36];   // [m][k], pad 4
    __shared__ float Bs[64][36];    // [n][k]
    __shared__ float s_bias[64];

    const int proj = blockIdx.z;
    const float* W    = (proj == 0) ? Wq : (proj == 1) ? Wk : Wv;
    const float* bias = (proj == 0) ? bq : (proj == 1) ? bk : bv;

    const int tid  = threadIdx.x;
    const int lane = tid & 31;
    const int w    = tid >> 5;
    const int g    = lane >> 2;      // group (row within fragment)
    const int cq   = lane & 3;       // thread-in-group (col within fragment)
    const int mw   = (w & 3) << 5;   // warp m offset (0..96)
    const int nw   = (w >> 2) << 5;  // warp n offset (0 or 32)
    const int m0   = blockIdx.y << 7;
    const int n0   = blockIdx.x << 6;

    if (tid < 64) s_bias[tid] = bias[n0 + tid];

    float acc[2][4][4] = {};   // [mt][nt][4]

    // prefetch chunk 0
    float4 pa[4], pb[2];
    #pragma unroll
    for (int i = 0; i < 4; i++) {
        const int idx = tid + (i << 8);
        pa[i] = *(const float4*)(A + (size_t)(m0 + (idx >> 3)) * 1024 + ((idx & 7) << 2));
    }
    #pragma unroll
    for (int i = 0; i < 2; i++) {
        const int idx = tid + (i << 8);
        pb[i] = *(const float4*)(W + (size_t)(n0 + (idx >> 3)) * 1024 + ((idx & 7) << 2));
    }

    for (int ch = 0; ch < 32; ++ch) {
        __syncthreads();
        #pragma unroll
        for (int i = 0; i < 4; i++) {
            const int idx = tid + (i << 8);
            float* p = &As[idx >> 3][(idx & 7) << 2];
            p[0] = tf32r(pa[i].x); p[1] = tf32r(pa[i].y);
            p[2] = tf32r(pa[i].z); p[3] = tf32r(pa[i].w);
        }
        #pragma unroll
        for (int i = 0; i < 2; i++) {
            const int idx = tid + (i << 8);
            float* p = &Bs[idx >> 3][(idx & 7) << 2];
            p[0] = tf32r(pb[i].x); p[1] = tf32r(pb[i].y);
            p[2] = tf32r(pb[i].z); p[3] = tf32r(pb[i].w);
        }
        __syncthreads();

        if (ch < 31) {
            const int k0 = (ch + 1) << 5;
            #pragma unroll
            for (int i = 0; i < 4; i++) {
                const int idx = tid + (i << 8);
                pa[i] = *(const float4*)(A + (size_t)(m0 + (idx >> 3)) * 1024 + k0 + ((idx & 7) << 2));
            }
            #pragma unroll
            for (int i = 0; i < 2; i++) {
                const int idx = tid + (i << 8);
                pb[i] = *(const float4*)(W + (size_t)(n0 + (idx >> 3)) * 1024 + k0 + ((idx & 7) << 2));
            }
        }

        #pragma unroll
        for (int ks = 0; ks < 4; ++ks) {
            const int kk = ks << 3;
            uint32_t a[2][4];
            #pragma unroll
            for (int mt = 0; mt < 2; mt++) {
                const int r = mw + (mt << 4) + g;
                a[mt][0] = fu(As[r][kk + cq]);
                a[mt][1] = fu(As[r + 8][kk + cq]);
                a[mt][2] = fu(As[r][kk + cq + 4]);
                a[mt][3] = fu(As[r + 8][kk + cq + 4]);
            }
            #pragma unroll
            for (int nt = 0; nt < 4; nt++) {
                const int r = nw + (nt << 3) + g;
                uint32_t bf[2] = { fu(Bs[r][kk + cq]), fu(Bs[r][kk + cq + 4]) };
                mma8(acc[0][nt], a[0], bf);
                mma8(acc[1][nt], a[1], bf);
            }
        }
    }

    // ---- epilogue ----
    const int h = blockIdx.x & 15;   // n-tile == head (64-wide)
    #pragma unroll
    for (int mt = 0; mt < 2; mt++) {
        const int m  = m0 + mw + (mt << 4) + g;
        const int b_ = m >> 11;
        const int s  = m & 2047;
        const int bh = b_ * 16 + h;
        #pragma unroll
        for (int nt = 0; nt < 4; nt++) {
            const int col = nw + (nt << 3) + (cq << 1);
            const float b0 = s_bias[col], b1 = s_bias[col + 1];
            if (proj < 2) {
                float* dst = (proj == 0) ? g_q : g_k;
                *(float2*)&dst[(size_t)(bh * 2048 + s) * 64 + col] =
                    make_float2(acc[mt][nt][0] + b0, acc[mt][nt][1] + b1);
                *(float2*)&dst[(size_t)(bh * 2048 + s + 8) * 64 + col] =
                    make_float2(acc[mt][nt][2] + b0, acc[mt][nt][3] + b1);
            } else {
                g_vT[(size_t)(bh * 64 + col)     * 2048 + s]     = acc[mt][nt][0] + b0;
                g_vT[(size_t)(bh * 64 + col + 1) * 2048 + s]     = acc[mt][nt][1] + b1;
                g_vT[(size_t)(bh * 64 + col)     * 2048 + s + 8] = acc[mt][nt][2] + b0;
                g_vT[(size_t)(bh * 64 + col + 1) * 2048 + s + 8] = acc[mt][nt][3] + b1;
            }
        }
    }
}

// ---------------------------------------------------------------------------
// Attention (tf32 mma both GEMMs). Block: 256 thr, 64 q x 64 dv output tile.
// Per 64-key tile: S = Q K^T (warps: 4 in q, 2 in key-half), exp*mask -> Ps,
// then acc += P @ V (warps: 4 in q, 2 in dv-half).
// ---------------------------------------------------------------------------
#define ATTN_SMEM_FLOATS (4 * 64 * 68 + 64 + 128)

__global__ __launch_bounds__(256)
void attn_kernel(const float* __restrict__ mask, float* __restrict__ out)
{
    extern __shared__ float sm[];
    float* Qs    = sm;               // [64 q ][68] cols = dk
    float* Ks    = Qs + 64 * 68;     // [64 key][68] cols = dk
    float* Vts   = Ks + 64 * 68;     // [64 dv][68] cols = key
    float* Ps    = Vts + 64 * 68;    // [64 q ][68] cols = key
    float* maskS = Ps + 64 * 68;     // [64]
    float* dsum  = maskS + 64;       // [2][64]

    const int tid  = threadIdx.x;
    const int lane = tid & 31;
    const int w    = tid >> 5;
    const int g    = lane >> 2;
    const int cq   = lane & 3;
    const int qw   = (w & 3) << 4;   // warp q offset (0..48)
    const int kh   = (w >> 2) << 5;  // warp key/dv half offset (0 or 32)
    const int q0   = blockIdx.x << 6;
    const int bh   = blockIdx.y;
    const int b    = bh >> 4;
    const int h    = bh & 15;

    // Q tile (once), tf32-rounded
    #pragma unroll
    for (int r = 0; r < 4; r++) {
        const int idx = tid + (r << 8);
        const int row = idx >> 4;
        const int c4  = (idx & 15) << 2;
        float4 v = *(const float4*)&g_q[(size_t)(bh * 2048 + q0 + row) * 64 + c4];
        *(float4*)&Qs[row * 68 + c4] =
            make_float4(tf32r(v.x), tf32r(v.y), tf32r(v.z), tf32r(v.w));
    }

    float acc[4][4] = {};     // PV accum: [dv n-tile][4]
    float rs_lo = 0.f, rs_hi = 0.f;

    for (int kt = 0; kt < 32; kt++) {
        const int k0 = kt << 6;
        __syncthreads();
        #pragma unroll
        for (int r = 0; r < 4; r++) {
            const int idx = tid + (r << 8);
            const int row = idx >> 4;
            const int c4  = (idx & 15) << 2;
            float4 kv = *(const float4*)&g_k[(size_t)(bh * 2048 + k0 + row) * 64 + c4];
            *(float4*)&Ks[row * 68 + c4] =
                make_float4(tf32r(kv.x), tf32r(kv.y), tf32r(kv.z), tf32r(kv.w));
            float4 vv = *(const float4*)&g_vT[(size_t)(bh * 64 + row) * 2048 + k0 + c4];
            *(float4*)&Vts[row * 68 + c4] =
                make_float4(tf32r(vv.x), tf32r(vv.y), tf32r(vv.z), tf32r(vv.w));
        }
        if (tid < 16)
            *(float4*)&maskS[tid << 2] = *(const float4*)&mask[b * 2048 + k0 + (tid << 2)];
        __syncthreads();

        // ---- S = Q K^T ----
        float s[4][4] = {};
        #pragma unroll
        for (int ks = 0; ks < 8; ks++) {
            const int kk = ks << 3;
            uint32_t a[4] = { fu(Qs[(qw + g) * 68 + kk + cq]),
                              fu(Qs[(qw + g + 8) * 68 + kk + cq]),
                              fu(Qs[(qw + g) * 68 + kk + cq + 4]),
                              fu(Qs[(qw + g + 8) * 68 + kk + cq + 4]) };
            #pragma unroll
            for (int nt = 0; nt < 4; nt++) {
                const int key = kh + (nt << 3) + g;
                uint32_t bf[2] = { fu(Ks[key * 68 + kk + cq]),
                                   fu(Ks[key * 68 + kk + cq + 4]) };
                mma8(s[nt], a, bf);
            }
        }

        // ---- P = exp(S/8)*mask, row sums, stage P (tf32) ----
        #pragma unroll
        for (int nt = 0; nt < 4; nt++) {
            const int col = kh + (nt << 3) + (cq << 1);
            const float m0 = maskS[col], m1 = maskS[col + 1];
            const float p00 = __expf(s[nt][0] * 0.125f) * m0;
            const float p01 = __expf(s[nt][1] * 0.125f) * m1;
            const float p10 = __expf(s[nt][2] * 0.125f) * m0;
            const float p11 = __expf(s[nt][3] * 0.125f) * m1;
            rs_lo += p00 + p01;
            rs_hi += p10 + p11;
            *(float2*)&Ps[(qw + g) * 68 + col]     = make_float2(tf32r(p00), tf32r(p01));
            *(float2*)&Ps[(qw + g + 8) * 68 + col] = make_float2(tf32r(p10), tf32r(p11));
        }
        __syncthreads();

        // ---- acc += P @ V ----
        #pragma unroll
        for (int ks = 0; ks < 8; ks++) {
            const int kk = ks << 3;
            uint32_t a[4] = { fu(Ps[(qw + g) * 68 + kk + cq]),
                              fu(Ps[(qw + g + 8) * 68 + kk + cq]),
                              fu(Ps[(qw + g) * 68 + kk + cq + 4]),
                              fu(Ps[(qw + g + 8) * 68 + kk + cq + 4]) };
            #pragma unroll
            for (int nt = 0; nt < 4; nt++) {
                const int dv = kh + (nt << 3) + g;
                uint32_t bf[2] = { fu(Vts[dv * 68 + kk + cq]),
                                   fu(Vts[dv * 68 + kk + cq + 4]) };
                mma8(acc[nt], a, bf);
            }
        }
    }

    // ---- denominator: reduce across thread-group, combine key-halves ----
    rs_lo += __shfl_xor_sync(0xffffffffu, rs_lo, 1);
    rs_lo += __shfl_xor_sync(0xffffffffu, rs_lo, 2);
    rs_hi += __shfl_xor_sync(0xffffffffu, rs_hi, 1);
    rs_hi += __shfl_xor_sync(0xffffffffu, rs_hi, 2);
    if (cq == 0) {
        dsum[(w >> 2) * 64 + qw + g]     = rs_lo;
        dsum[(w >> 2) * 64 + qw + g + 8] = rs_hi;
    }
    __syncthreads();

    const float inv_lo = 1.0f / (dsum[qw + g]     + dsum[64 + qw + g]     + 1e-8f);
    const float inv_hi = 1.0f / (dsum[qw + g + 8] + dsum[64 + qw + g + 8] + 1e-8f);

    // out[b][q][h*64+dv]
    const int q_lo = q0 + qw + g;
    #pragma unroll
    for (int nt = 0; nt < 4; nt++) {
        const int dv = kh + (nt << 3) + (cq << 1);
        *(float2*)&out[(size_t)((b * 2048 + q_lo) * 16 + h) * 64 + dv] =
            make_float2(acc[nt][0] * inv_lo, acc[nt][1] * inv_lo);
        *(float2*)&out[(size_t)((b * 2048 + q_lo + 8) * 16 + h) * 64 + dv] =
            make_float2(acc[nt][2] * inv_hi, acc[nt][3] * inv_hi);
    }
}

// ---------------------------------------------------------------------------
extern "C" void kernel_launch(void* const* d_in, const int* in_sizes, int n_in,
                              void* d_out, int out_size)
{
    const float* Q    = (const float*)d_in[0];
    const float* mask = (const float*)d_in[1];
    const float* Wq   = (const float*)d_in[2];
    const float* bq   = (const float*)d_in[3];
    const float* Wk   = (const float*)d_in[4];
    const float* bk   = (const float*)d_in[5];
    const float* Wv   = (const float*)d_in[6];
    const float* bv   = (const float*)d_in[7];
    float* out = (float*)d_out;

    cudaFuncSetAttribute(attn_kernel,
                         cudaFuncAttributeMaxDynamicSharedMemorySize,
                         ATTN_SMEM_FLOATS * (int)sizeof(float));

    proj_kernel<<<dim3(16, 32, 3), 256>>>(Q, Wq, bq, Wk, bk, Wv, bv);
    attn_kernel<<<dim3(32, 32), 256, ATTN_SMEM_FLOATS * sizeof(float)>>>(mask, out);
}

// round 4
// speedup vs baseline: 2.8661x; 1.5382x over previous
#include <cuda_runtime.h>
#include <cstdint>

// Shapes: Q[2,2048,1024], mask[2,2048], W_*[1024,1024], b_*[1024], out[2,2048,1024] fp32
// Scratch:
//   g_q, g_k : [bh][s][64]            (A row-major / B col-major for QK^T)
//   g_vT     : [bh][64(dv)][2048(s)]  (B col-major for P@V)
__device__ float g_q [2 * 16 * 2048 * 64];
__device__ float g_k [2 * 16 * 2048 * 64];
__device__ float g_vT[2 * 16 * 64 * 2048];

// ---------------------------------------------------------------------------
// helpers
// ---------------------------------------------------------------------------
__device__ __forceinline__ float tf32r(float x) {
    uint32_t u;
    asm("cvt.rna.tf32.f32 %0, %1;" : "=r"(u) : "f"(x));
    return __uint_as_float(u);
}
__device__ __forceinline__ uint32_t smem_u32(const void* p) {
    uint32_t a;
    asm("{ .reg .u64 t; cvta.to.shared.u64 t, %1; cvt.u32.u64 %0, t; }" : "=r"(a) : "l"(p));
    return a;
}
// ldmatrix x4: four 8x8 b16 matrices == four 8x4 tf32 matrices.
// lane>>3 selects matrix, lane&7 selects row within it.
__device__ __forceinline__ void ldsm4(uint32_t* r, uint32_t addr) {
    asm volatile("ldmatrix.sync.aligned.m8n8.x4.shared.b16 {%0,%1,%2,%3}, [%4];"
                 : "=r"(r[0]), "=r"(r[1]), "=r"(r[2]), "=r"(r[3]) : "r"(addr));
}
// D += A(m16k8,row) * B(k8n8,col)   tf32 inputs, f32 accum
__device__ __forceinline__ void mma8(float* c, const uint32_t* a, const uint32_t* b) {
    asm volatile(
        "mma.sync.aligned.m16n8k8.row.col.f32.tf32.tf32.f32 "
        "{%0,%1,%2,%3}, {%4,%5,%6,%7}, {%8,%9}, {%0,%1,%2,%3};"
        : "+f"(c[0]), "+f"(c[1]), "+f"(c[2]), "+f"(c[3])
        : "r"(a[0]), "r"(a[1]), "r"(a[2]), "r"(a[3]), "r"(b[0]), "r"(b[1]));
}

// A-operand ldmatrix address: 16-row tile at rowBase, k-chunk col base kk added later.
// matrix0: rows 0-7 / cols 0-3; m1: rows 8-15 / cols 0-3; m2: rows 0-7 / cols 4-7; m3: rows 8-15 / cols 4-7.
__device__ __forceinline__ uint32_t a_addr(const float* base, int rowBase, int stride, int lane) {
    const int row = rowBase + ((lane >> 3) & 1) * 8 + (lane & 7);
    const int col = (lane >> 4) << 2;
    return smem_u32(base + row * stride + col);
}
// B-pair ldmatrix address: two 8-row n-tiles (rowBase, rowBase+8).
// m0: rows 0-7/cols 0-3; m1: rows 0-7/cols 4-7; m2: rows 8-15/cols 0-3; m3: rows 8-15/cols 4-7.
// => regs {r0,r1} = fragment for n-tile 0, {r2,r3} = n-tile 1.
__device__ __forceinline__ uint32_t b_addr(const float* base, int rowBase, int stride, int lane) {
    const int sel = lane >> 3;
    const int row = rowBase + (sel >> 1) * 8 + (lane & 7);
    const int col = (sel & 1) << 2;
    return smem_u32(base + row * stride + col);
}

// ---------------------------------------------------------------------------
// Projection GEMM (tf32 mma): C[m,n] = sum_k A[m,k]*W[n,k] + bias[n]
// Block: 256 thr (8 warps, 4m x 2n), tile M=128 N=64, K-chunk 32.
// grid = (16 n-tiles, 32 m-tiles, 3 proj)
// ---------------------------------------------------------------------------
__global__ __launch_bounds__(256)
void proj_kernel(const float* __restrict__ A,
                 const float* __restrict__ Wq, const float* __restrict__ bq,
                 const float* __restrict__ Wk, const float* __restrict__ bk,
                 const float* __restrict__ Wv, const float* __restrict__ bv)
{
    __shared__ float As[128][36];   // [m][k], pad 4 (stride 144B, 16B-multiple)
    __shared__ float Bs[64][36];    // [n][k]
    __shared__ float s_bias[64];

    const int proj = blockIdx.z;
    const float* W    = (proj == 0) ? Wq : (proj == 1) ? Wk : Wv;
    const float* bias = (proj == 0) ? bq : (proj == 1) ? bk : bv;

    const int tid  = threadIdx.x;
    const int lane = tid & 31;
    const int w    = tid >> 5;
    const int g    = lane >> 2;
    const int cq   = lane & 3;
    const int mw   = (w & 3) << 5;   // warp m offset
    const int nw   = (w >> 2) << 5;  // warp n offset
    const int m0   = blockIdx.y << 7;
    const int n0   = blockIdx.x << 6;

    if (tid < 64) s_bias[tid] = bias[n0 + tid];

    // ldmatrix base addresses (k-chunk offset added per step)
    const uint32_t aAdr0 = a_addr(&As[0][0], mw,      36, lane);
    const uint32_t aAdr1 = a_addr(&As[0][0], mw + 16, 36, lane);
    const uint32_t bAdr0 = b_addr(&Bs[0][0], nw,      36, lane);
    const uint32_t bAdr1 = b_addr(&Bs[0][0], nw + 16, 36, lane);

    float acc[2][4][4] = {};

    float4 pa[4], pb[2];
    #pragma unroll
    for (int i = 0; i < 4; i++) {
        const int idx = tid + (i << 8);
        pa[i] = *(const float4*)(A + (size_t)(m0 + (idx >> 3)) * 1024 + ((idx & 7) << 2));
    }
    #pragma unroll
    for (int i = 0; i < 2; i++) {
        const int idx = tid + (i << 8);
        pb[i] = *(const float4*)(W + (size_t)(n0 + (idx >> 3)) * 1024 + ((idx & 7) << 2));
    }

    for (int ch = 0; ch < 32; ++ch) {
        __syncthreads();
        #pragma unroll
        for (int i = 0; i < 4; i++) {
            const int idx = tid + (i << 8);
            *(float4*)&As[idx >> 3][(idx & 7) << 2] =
                make_float4(tf32r(pa[i].x), tf32r(pa[i].y), tf32r(pa[i].z), tf32r(pa[i].w));
        }
        #pragma unroll
        for (int i = 0; i < 2; i++) {
            const int idx = tid + (i << 8);
            *(float4*)&Bs[idx >> 3][(idx & 7) << 2] =
                make_float4(tf32r(pb[i].x), tf32r(pb[i].y), tf32r(pb[i].z), tf32r(pb[i].w));
        }
        __syncthreads();

        if (ch < 31) {
            const int k0 = (ch + 1) << 5;
            #pragma unroll
            for (int i = 0; i < 4; i++) {
                const int idx = tid + (i << 8);
                pa[i] = *(const float4*)(A + (size_t)(m0 + (idx >> 3)) * 1024 + k0 + ((idx & 7) << 2));
            }
            #pragma unroll
            for (int i = 0; i < 2; i++) {
                const int idx = tid + (i << 8);
                pb[i] = *(const float4*)(W + (size_t)(n0 + (idx >> 3)) * 1024 + k0 + ((idx & 7) << 2));
            }
        }

        #pragma unroll
        for (int ks = 0; ks < 4; ++ks) {
            const uint32_t koff = (uint32_t)(ks << 5);   // 8 floats = 32 bytes
            uint32_t a0[4], a1[4], b0[4], b1[4];
            ldsm4(a0, aAdr0 + koff);
            ldsm4(a1, aAdr1 + koff);
            ldsm4(b0, bAdr0 + koff);
            ldsm4(b1, bAdr1 + koff);
            mma8(acc[0][0], a0, b0);     mma8(acc[1][0], a1, b0);
            mma8(acc[0][1], a0, b0 + 2); mma8(acc[1][1], a1, b0 + 2);
            mma8(acc[0][2], a0, b1);     mma8(acc[1][2], a1, b1);
            mma8(acc[0][3], a0, b1 + 2); mma8(acc[1][3], a1, b1 + 2);
        }
    }

    // ---- epilogue ----
    const int h = blockIdx.x & 15;
    #pragma unroll
    for (int mt = 0; mt < 2; mt++) {
        const int m  = m0 + mw + (mt << 4) + g;
        const int b_ = m >> 11;
        const int s  = m & 2047;
        const int bh = b_ * 16 + h;
        #pragma unroll
        for (int nt = 0; nt < 4; nt++) {
            const int col = nw + (nt << 3) + (cq << 1);
            const float b0 = s_bias[col], b1 = s_bias[col + 1];
            if (proj < 2) {
                float* dst = (proj == 0) ? g_q : g_k;
                *(float2*)&dst[(size_t)(bh * 2048 + s) * 64 + col] =
                    make_float2(acc[mt][nt][0] + b0, acc[mt][nt][1] + b1);
                *(float2*)&dst[(size_t)(bh * 2048 + s + 8) * 64 + col] =
                    make_float2(acc[mt][nt][2] + b0, acc[mt][nt][3] + b1);
            } else {
                g_vT[(size_t)(bh * 64 + col)     * 2048 + s]     = acc[mt][nt][0] + b0;
                g_vT[(size_t)(bh * 64 + col + 1) * 2048 + s]     = acc[mt][nt][1] + b1;
                g_vT[(size_t)(bh * 64 + col)     * 2048 + s + 8] = acc[mt][nt][2] + b0;
                g_vT[(size_t)(bh * 64 + col + 1) * 2048 + s + 8] = acc[mt][nt][3] + b1;
            }
        }
    }
}

// ---------------------------------------------------------------------------
// Attention (tf32 mma both GEMMs), fragment loads via ldmatrix.
// Block: 256 thr, 64 q x 64 dv output tile, stream 64-key tiles.
// ---------------------------------------------------------------------------
#define ATTN_SMEM_FLOATS (4 * 64 * 68 + 64 + 128)

__global__ __launch_bounds__(256)
void attn_kernel(const float* __restrict__ mask, float* __restrict__ out)
{
    extern __shared__ float sm[];
    float* Qs    = sm;               // [64 q ][68] cols = dk
    float* Ks    = Qs + 64 * 68;     // [64 key][68] cols = dk
    float* Vts   = Ks + 64 * 68;     // [64 dv][68] cols = key
    float* Ps    = Vts + 64 * 68;    // [64 q ][68] cols = key
    float* maskS = Ps + 64 * 68;     // [64]
    float* dsum  = maskS + 64;       // [2][64]

    const int tid  = threadIdx.x;
    const int lane = tid & 31;
    const int w    = tid >> 5;
    const int g    = lane >> 2;
    const int cq   = lane & 3;
    const int qw   = (w & 3) << 4;   // warp q offset
    const int kh   = (w >> 2) << 5;  // warp key/dv half offset
    const int q0   = blockIdx.x << 6;
    const int bh   = blockIdx.y;
    const int b    = bh >> 4;
    const int h    = bh & 15;

    const uint32_t qAdr  = a_addr(Qs,  qw, 68, lane);
    const uint32_t pAdr  = a_addr(Ps,  qw, 68, lane);
    const uint32_t kAdr0 = b_addr(Ks,  kh,      68, lane);
    const uint32_t kAdr1 = b_addr(Ks,  kh + 16, 68, lane);
    const uint32_t vAdr0 = b_addr(Vts, kh,      68, lane);
    const uint32_t vAdr1 = b_addr(Vts, kh + 16, 68, lane);

    #pragma unroll
    for (int r = 0; r < 4; r++) {
        const int idx = tid + (r << 8);
        const int row = idx >> 4;
        const int c4  = (idx & 15) << 2;
        float4 v = *(const float4*)&g_q[(size_t)(bh * 2048 + q0 + row) * 64 + c4];
        *(float4*)&Qs[row * 68 + c4] =
            make_float4(tf32r(v.x), tf32r(v.y), tf32r(v.z), tf32r(v.w));
    }

    float acc[4][4] = {};
    float rs_lo = 0.f, rs_hi = 0.f;

    for (int kt = 0; kt < 32; kt++) {
        const int k0 = kt << 6;
        __syncthreads();
        #pragma unroll
        for (int r = 0; r < 4; r++) {
            const int idx = tid + (r << 8);
            const int row = idx >> 4;
            const int c4  = (idx & 15) << 2;
            float4 kv = *(const float4*)&g_k[(size_t)(bh * 2048 + k0 + row) * 64 + c4];
            *(float4*)&Ks[row * 68 + c4] =
                make_float4(tf32r(kv.x), tf32r(kv.y), tf32r(kv.z), tf32r(kv.w));
            float4 vv = *(const float4*)&g_vT[(size_t)(bh * 64 + row) * 2048 + k0 + c4];
            *(float4*)&Vts[row * 68 + c4] =
                make_float4(tf32r(vv.x), tf32r(vv.y), tf32r(vv.z), tf32r(vv.w));
        }
        if (tid < 16)
            *(float4*)&maskS[tid << 2] = *(const float4*)&mask[b * 2048 + k0 + (tid << 2)];
        __syncthreads();

        // ---- S = Q K^T ----
        float s[4][4] = {};
        #pragma unroll
        for (int ks = 0; ks < 8; ks++) {
            const uint32_t koff = (uint32_t)(ks << 5);
            uint32_t a[4], b0[4], b1[4];
            ldsm4(a,  qAdr  + koff);
            ldsm4(b0, kAdr0 + koff);
            ldsm4(b1, kAdr1 + koff);
            mma8(s[0], a, b0);
            mma8(s[1], a, b0 + 2);
            mma8(s[2], a, b1);
            mma8(s[3], a, b1 + 2);
        }

        // ---- P = exp(S/8)*mask, row sums, stage P (tf32) ----
        #pragma unroll
        for (int nt = 0; nt < 4; nt++) {
            const int col = kh + (nt << 3) + (cq << 1);
            const float m0 = maskS[col], m1 = maskS[col + 1];
            const float p00 = __expf(s[nt][0] * 0.125f) * m0;
            const float p01 = __expf(s[nt][1] * 0.125f) * m1;
            const float p10 = __expf(s[nt][2] * 0.125f) * m0;
            const float p11 = __expf(s[nt][3] * 0.125f) * m1;
            rs_lo += p00 + p01;
            rs_hi += p10 + p11;
            *(float2*)&Ps[(qw + g) * 68 + col]     = make_float2(tf32r(p00), tf32r(p01));
            *(float2*)&Ps[(qw + g + 8) * 68 + col] = make_float2(tf32r(p10), tf32r(p11));
        }
        __syncthreads();

        // ---- acc += P @ V ----
        #pragma unroll
        for (int ks = 0; ks < 8; ks++) {
            const uint32_t koff = (uint32_t)(ks << 5);
            uint32_t a[4], b0[4], b1[4];
            ldsm4(a,  pAdr  + koff);
            ldsm4(b0, vAdr0 + koff);
            ldsm4(b1, vAdr1 + koff);
            mma8(acc[0], a, b0);
            mma8(acc[1], a, b0 + 2);
            mma8(acc[2], a, b1);
            mma8(acc[3], a, b1 + 2);
        }
    }

    // ---- denominator ----
    rs_lo += __shfl_xor_sync(0xffffffffu, rs_lo, 1);
    rs_lo += __shfl_xor_sync(0xffffffffu, rs_lo, 2);
    rs_hi += __shfl_xor_sync(0xffffffffu, rs_hi, 1);
    rs_hi += __shfl_xor_sync(0xffffffffu, rs_hi, 2);
    if (cq == 0) {
        dsum[(w >> 2) * 64 + qw + g]     = rs_lo;
        dsum[(w >> 2) * 64 + qw + g + 8] = rs_hi;
    }
    __syncthreads();

    const float inv_lo = 1.0f / (dsum[qw + g]     + dsum[64 + qw + g]     + 1e-8f);
    const float inv_hi = 1.0f / (dsum[qw + g + 8] + dsum[64 + qw + g + 8] + 1e-8f);

    const int q_lo = q0 + qw + g;
    #pragma unroll
    for (int nt = 0; nt < 4; nt++) {
        const int dv = kh + (nt << 3) + (cq << 1);
        *(float2*)&out[(size_t)((b * 2048 + q_lo) * 16 + h) * 64 + dv] =
            make_float2(acc[nt][0] * inv_lo, acc[nt][1] * inv_lo);
        *(float2*)&out[(size_t)((b * 2048 + q_lo + 8) * 16 + h) * 64 + dv] =
            make_float2(acc[nt][2] * inv_hi, acc[nt][3] * inv_hi);
    }
}

// ---------------------------------------------------------------------------
extern "C" void kernel_launch(void* const* d_in, const int* in_sizes, int n_in,
                              void* d_out, int out_size)
{
    const float* Q    = (const float*)d_in[0];
    const float* mask = (const float*)d_in[1];
    const float* Wq   = (const float*)d_in[2];
    const float* bq   = (const float*)d_in[3];
    const float* Wk   = (const float*)d_in[4];
    const float* bk   = (const float*)d_in[5];
    const float* Wv   = (const float*)d_in[6];
    const float* bv   = (const float*)d_in[7];
    float* out = (float*)d_out;

    cudaFuncSetAttribute(attn_kernel,
                         cudaFuncAttributeMaxDynamicSharedMemorySize,
                         ATTN_SMEM_FLOATS * (int)sizeof(float));

    proj_kernel<<<dim3(16, 32, 3), 256>>>(Q, Wq, bq, Wk, bk, Wv, bv);
    attn_kernel<<<dim3(32, 32), 256, ATTN_SMEM_FLOATS * sizeof(float)>>>(mask, out);
}

// round 5
// speedup vs baseline: 3.4315x; 1.1973x over previous
#include <cuda_runtime.h>
#include <cstdint>

// Shapes: Q[2,2048,1024], mask[2,2048], W_*[1024,1024], b_*[1024], out[2,2048,1024] fp32
// Scratch (stored PRE-ROUNDED to tf32 by proj epilogue):
//   g_q, g_k : [bh][s][64]            (A row-major / B col-major for QK^T)
//   g_vT     : [bh][64(dv)][2048(s)]  (B col-major for P@V)
__device__ float g_q [2 * 16 * 2048 * 64];
__device__ float g_k [2 * 16 * 2048 * 64];
__device__ float g_vT[2 * 16 * 64 * 2048];

// ---------------------------------------------------------------------------
// helpers
// ---------------------------------------------------------------------------
__device__ __forceinline__ float tf32r(float x) {
    uint32_t u;
    asm("cvt.rna.tf32.f32 %0, %1;" : "=r"(u) : "f"(x));
    return __uint_as_float(u);
}
__device__ __forceinline__ uint32_t fu(float x) { return __float_as_uint(x); }
__device__ __forceinline__ uint32_t smem_u32(const void* p) {
    uint32_t a;
    asm("{ .reg .u64 t; cvta.to.shared.u64 t, %1; cvt.u32.u64 %0, t; }" : "=r"(a) : "l"(p));
    return a;
}
__device__ __forceinline__ void ldsm4(uint32_t* r, uint32_t addr) {
    asm volatile("ldmatrix.sync.aligned.m8n8.x4.shared.b16 {%0,%1,%2,%3}, [%4];"
                 : "=r"(r[0]), "=r"(r[1]), "=r"(r[2]), "=r"(r[3]) : "r"(addr));
}
__device__ __forceinline__ void mma8(float* c, const uint32_t* a, const uint32_t* b) {
    asm volatile(
        "mma.sync.aligned.m16n8k8.row.col.f32.tf32.tf32.f32 "
        "{%0,%1,%2,%3}, {%4,%5,%6,%7}, {%8,%9}, {%0,%1,%2,%3};"
        : "+f"(c[0]), "+f"(c[1]), "+f"(c[2]), "+f"(c[3])
        : "r"(a[0]), "r"(a[1]), "r"(a[2]), "r"(a[3]), "r"(b[0]), "r"(b[1]));
}
__device__ __forceinline__ void cpa16(uint32_t dst, const void* src) {
    asm volatile("cp.async.ca.shared.global [%0], [%1], 16;" :: "r"(dst), "l"(src));
}
#define CP_COMMIT() asm volatile("cp.async.commit_group;" ::: "memory")
#define CP_WAIT1()  asm volatile("cp.async.wait_group 1;" ::: "memory")

// A-operand ldmatrix address (16-row tile at rowBase)
__device__ __forceinline__ uint32_t a_addr(const float* base, int rowBase, int stride, int lane) {
    const int row = rowBase + ((lane >> 3) & 1) * 8 + (lane & 7);
    const int col = (lane >> 4) << 2;
    return smem_u32(base + row * stride + col);
}
// B-pair ldmatrix address (two 8-row n-tiles at rowBase, rowBase+8)
__device__ __forceinline__ uint32_t b_addr(const float* base, int rowBase, int stride, int lane) {
    const int sel = lane >> 3;
    const int row = rowBase + (sel >> 1) * 8 + (lane & 7);
    const int col = (sel & 1) << 2;
    return smem_u32(base + row * stride + col);
}

// ---------------------------------------------------------------------------
// Projection GEMM (tf32 mma): C[m,n] = sum_k A[m,k]*W[n,k] + bias[n]
// Block 256 thr (8 warps, 4m x 2n), tile M=128 N=64, K-chunk 32.
// Epilogue stores tf32-ROUNDED values (attention consumes them raw via cp.async).
// ---------------------------------------------------------------------------
__global__ __launch_bounds__(256)
void proj_kernel(const float* __restrict__ A,
                 const float* __restrict__ Wq, const float* __restrict__ bq,
                 const float* __restrict__ Wk, const float* __restrict__ bk,
                 const float* __restrict__ Wv, const float* __restrict__ bv)
{
    __shared__ float As[128][36];
    __shared__ float Bs[64][36];
    __shared__ float s_bias[64];

    const int proj = blockIdx.z;
    const float* W    = (proj == 0) ? Wq : (proj == 1) ? Wk : Wv;
    const float* bias = (proj == 0) ? bq : (proj == 1) ? bk : bv;

    const int tid  = threadIdx.x;
    const int lane = tid & 31;
    const int w    = tid >> 5;
    const int g    = lane >> 2;
    const int cq   = lane & 3;
    const int mw   = (w & 3) << 5;
    const int nw   = (w >> 2) << 5;
    const int m0   = blockIdx.y << 7;
    const int n0   = blockIdx.x << 6;

    if (tid < 64) s_bias[tid] = bias[n0 + tid];

    const uint32_t aAdr0 = a_addr(&As[0][0], mw,      36, lane);
    const uint32_t aAdr1 = a_addr(&As[0][0], mw + 16, 36, lane);
    const uint32_t bAdr0 = b_addr(&Bs[0][0], nw,      36, lane);
    const uint32_t bAdr1 = b_addr(&Bs[0][0], nw + 16, 36, lane);

    float acc[2][4][4] = {};

    float4 pa[4], pb[2];
    #pragma unroll
    for (int i = 0; i < 4; i++) {
        const int idx = tid + (i << 8);
        pa[i] = *(const float4*)(A + (size_t)(m0 + (idx >> 3)) * 1024 + ((idx & 7) << 2));
    }
    #pragma unroll
    for (int i = 0; i < 2; i++) {
        const int idx = tid + (i << 8);
        pb[i] = *(const float4*)(W + (size_t)(n0 + (idx >> 3)) * 1024 + ((idx & 7) << 2));
    }

    for (int ch = 0; ch < 32; ++ch) {
        __syncthreads();
        #pragma unroll
        for (int i = 0; i < 4; i++) {
            const int idx = tid + (i << 8);
            *(float4*)&As[idx >> 3][(idx & 7) << 2] =
                make_float4(tf32r(pa[i].x), tf32r(pa[i].y), tf32r(pa[i].z), tf32r(pa[i].w));
        }
        #pragma unroll
        for (int i = 0; i < 2; i++) {
            const int idx = tid + (i << 8);
            *(float4*)&Bs[idx >> 3][(idx & 7) << 2] =
                make_float4(tf32r(pb[i].x), tf32r(pb[i].y), tf32r(pb[i].z), tf32r(pb[i].w));
        }
        __syncthreads();

        if (ch < 31) {
            const int k0 = (ch + 1) << 5;
            #pragma unroll
            for (int i = 0; i < 4; i++) {
                const int idx = tid + (i << 8);
                pa[i] = *(const float4*)(A + (size_t)(m0 + (idx >> 3)) * 1024 + k0 + ((idx & 7) << 2));
            }
            #pragma unroll
            for (int i = 0; i < 2; i++) {
                const int idx = tid + (i << 8);
                pb[i] = *(const float4*)(W + (size_t)(n0 + (idx >> 3)) * 1024 + k0 + ((idx & 7) << 2));
            }
        }

        #pragma unroll
        for (int ks = 0; ks < 4; ++ks) {
            const uint32_t koff = (uint32_t)(ks << 5);
            uint32_t a0[4], a1[4], b0[4], b1[4];
            ldsm4(a0, aAdr0 + koff);
            ldsm4(a1, aAdr1 + koff);
            ldsm4(b0, bAdr0 + koff);
            ldsm4(b1, bAdr1 + koff);
            mma8(acc[0][0], a0, b0);     mma8(acc[1][0], a1, b0);
            mma8(acc[0][1], a0, b0 + 2); mma8(acc[1][1], a1, b0 + 2);
            mma8(acc[0][2], a0, b1);     mma8(acc[1][2], a1, b1);
            mma8(acc[0][3], a0, b1 + 2); mma8(acc[1][3], a1, b1 + 2);
        }
    }

    // ---- epilogue (tf32-rounded stores) ----
    const int h = blockIdx.x & 15;
    #pragma unroll
    for (int mt = 0; mt < 2; mt++) {
        const int m  = m0 + mw + (mt << 4) + g;
        const int b_ = m >> 11;
        const int s  = m & 2047;
        const int bh = b_ * 16 + h;
        #pragma unroll
        for (int nt = 0; nt < 4; nt++) {
            const int col = nw + (nt << 3) + (cq << 1);
            const float b0 = s_bias[col], b1 = s_bias[col + 1];
            if (proj < 2) {
                float* dst = (proj == 0) ? g_q : g_k;
                *(float2*)&dst[(size_t)(bh * 2048 + s) * 64 + col] =
                    make_float2(tf32r(acc[mt][nt][0] + b0), tf32r(acc[mt][nt][1] + b1));
                *(float2*)&dst[(size_t)(bh * 2048 + s + 8) * 64 + col] =
                    make_float2(tf32r(acc[mt][nt][2] + b0), tf32r(acc[mt][nt][3] + b1));
            } else {
                g_vT[(size_t)(bh * 64 + col)     * 2048 + s]     = tf32r(acc[mt][nt][0] + b0);
                g_vT[(size_t)(bh * 64 + col + 1) * 2048 + s]     = tf32r(acc[mt][nt][1] + b1);
                g_vT[(size_t)(bh * 64 + col)     * 2048 + s + 8] = tf32r(acc[mt][nt][2] + b0);
                g_vT[(size_t)(bh * 64 + col + 1) * 2048 + s + 8] = tf32r(acc[mt][nt][3] + b1);
            }
        }
    }
}

// ---------------------------------------------------------------------------
// Attention v3: 256 thr, block tile = 128 q x 64 keys per kt.
// Warp = 16 q x ALL 64 keys: S accum stays in regs; PV A-fragments built via
// register shuffle transpose (no P smem round-trip). cp.async double-buffered K/V.
// ---------------------------------------------------------------------------
#define KV_STAGE  (64 * 68)                       // floats per K or V stage
#define ATTN_SMEM_FLOATS (128 * 68 + 4 * KV_STAGE + 2 * 64)

__global__ __launch_bounds__(256, 2)
void attn_kernel(const float* __restrict__ mask, float* __restrict__ out)
{
    extern __shared__ float sm[];
    float* Qs    = sm;                       // [128 q][68]
    float* Ksm   = Qs + 128 * 68;            // [2][64 key][68]
    float* Vsm   = Ksm + 2 * KV_STAGE;       // [2][64 dv ][68]
    float* maskS = Vsm + 2 * KV_STAGE;       // [2][64]

    const int tid  = threadIdx.x;
    const int lane = tid & 31;
    const int w    = tid >> 5;
    const int g    = lane >> 2;
    const int cq   = lane & 3;
    const int qw   = w << 4;                 // warp q offset (0..112)
    const int q0   = blockIdx.x << 7;        // 128-q block
    const int bh   = blockIdx.y;
    const int b    = bh >> 4;
    const int h    = bh & 15;

    const uint32_t uQ = smem_u32(Qs);
    const uint32_t uK = smem_u32(Ksm);
    const uint32_t uV = smem_u32(Vsm);
    const uint32_t uM = smem_u32(maskS);

    const uint32_t qAdr = a_addr(Qs, qw, 68, lane);
    uint32_t kAdr[4], vAdr[4];
    #pragma unroll
    for (int j = 0; j < 4; j++) {
        kAdr[j] = b_addr(Ksm, 16 * j, 68, lane);
        vAdr[j] = b_addr(Vsm, 16 * j, 68, lane);
    }

    const int row4 = tid >> 4;               // 0..15 used per 256-chunk slice
    const int c4   = (tid & 15) << 2;

    // ---- preload: Q (8 chunks) + tile0 -> group0 ; tile1 -> group1 ----
    #pragma unroll
    for (int i = 0; i < 8; i++) {
        const int row = row4 + (i << 4);
        cpa16(uQ + (uint32_t)(row * 68 + c4) * 4,
              &g_q[(size_t)(bh * 2048 + q0 + row) * 64 + c4]);
    }
    #pragma unroll
    for (int i = 0; i < 4; i++) {
        const int row = row4 + (i << 4);
        cpa16(uK + (uint32_t)(row * 68 + c4) * 4,
              &g_k[(size_t)(bh * 2048 + row) * 64 + c4]);
        cpa16(uV + (uint32_t)(row * 68 + c4) * 4,
              &g_vT[(size_t)(bh * 64 + row) * 2048 + c4]);
    }
    if (tid < 16) cpa16(uM + (uint32_t)(tid << 2) * 4, &mask[b * 2048 + (tid << 2)]);
    CP_COMMIT();
    #pragma unroll
    for (int i = 0; i < 4; i++) {
        const int row = row4 + (i << 4);
        cpa16(uK + (uint32_t)(KV_STAGE + row * 68 + c4) * 4,
              &g_k[(size_t)(bh * 2048 + 64 + row) * 64 + c4]);
        cpa16(uV + (uint32_t)(KV_STAGE + row * 68 + c4) * 4,
              &g_vT[(size_t)(bh * 64 + row) * 2048 + 64 + c4]);
    }
    if (tid < 16) cpa16(uM + (uint32_t)(64 + (tid << 2)) * 4, &mask[b * 2048 + 64 + (tid << 2)]);
    CP_COMMIT();
    CP_WAIT1();
    __syncthreads();

    float acc[8][4] = {};
    float rs_lo = 0.f, rs_hi = 0.f;
    const uint32_t srcA = (uint32_t)((lane & ~3) | (cq >> 1));
    const uint32_t srcB = srcA + 2;
    const bool odd = cq & 1;

    for (int kt = 0; kt < 32; kt++) {
        const int cur = kt & 1;
        const uint32_t stoff = (uint32_t)(cur * KV_STAGE) * 4;

        // ---- S = Q K^T : warp covers 16q x 64 keys ----
        float s[8][4] = {};
        #pragma unroll
        for (int ks = 0; ks < 8; ks++) {
            const uint32_t koff = (uint32_t)(ks << 5);
            uint32_t a[4];
            ldsm4(a, qAdr + koff);
            #pragma unroll
            for (int j = 0; j < 4; j++) {
                uint32_t bb[4];
                ldsm4(bb, kAdr[j] + stoff + koff);
                mma8(s[2 * j],     a, bb);
                mma8(s[2 * j + 1], a, bb + 2);
            }
        }

        // ---- P = exp(S/8)*mask (in regs), row sums ----
        #pragma unroll
        for (int nt = 0; nt < 8; nt++) {
            const int col = (nt << 3) + (cq << 1);
            const float2 mm = *(const float2*)&maskS[cur * 64 + col];
            const float p00 = __expf(s[nt][0] * 0.125f) * mm.x;
            const float p01 = __expf(s[nt][1] * 0.125f) * mm.y;
            const float p10 = __expf(s[nt][2] * 0.125f) * mm.x;
            const float p11 = __expf(s[nt][3] * 0.125f) * mm.y;
            rs_lo += p00 + p01;
            rs_hi += p10 + p11;
            s[nt][0] = p00; s[nt][1] = p01; s[nt][2] = p10; s[nt][3] = p11;
        }

        // ---- acc += P @ V : A-fragments via register shuffle transpose ----
        #pragma unroll
        for (int ks = 0; ks < 8; ks++) {
            const float x0 = __shfl_sync(0xffffffffu, s[ks][0], srcA);
            const float x1 = __shfl_sync(0xffffffffu, s[ks][1], srcA);
            const float y0 = __shfl_sync(0xffffffffu, s[ks][2], srcA);
            const float y1 = __shfl_sync(0xffffffffu, s[ks][3], srcA);
            const float z0 = __shfl_sync(0xffffffffu, s[ks][0], srcB);
            const float z1 = __shfl_sync(0xffffffffu, s[ks][1], srcB);
            const float w0 = __shfl_sync(0xffffffffu, s[ks][2], srcB);
            const float w1 = __shfl_sync(0xffffffffu, s[ks][3], srcB);
            uint32_t a[4] = { fu(tf32r(odd ? x1 : x0)), fu(tf32r(odd ? y1 : y0)),
                              fu(tf32r(odd ? z1 : z0)), fu(tf32r(odd ? w1 : w0)) };
            const uint32_t koff = (uint32_t)(ks << 5);
            #pragma unroll
            for (int j = 0; j < 4; j++) {
                uint32_t bb[4];
                ldsm4(bb, vAdr[j] + stoff + koff);
                mma8(acc[2 * j],     a, bb);
                mma8(acc[2 * j + 1], a, bb + 2);
            }
        }

        // ---- pipeline: refill this stage with tile kt+2 ----
        __syncthreads();
        if (kt + 2 < 32) {
            const int kn = (kt + 2) << 6;
            #pragma unroll
            for (int i = 0; i < 4; i++) {
                const int row = row4 + (i << 4);
                cpa16(uK + stoff + (uint32_t)(row * 68 + c4) * 4,
                      &g_k[(size_t)(bh * 2048 + kn + row) * 64 + c4]);
                cpa16(uV + stoff + (uint32_t)(row * 68 + c4) * 4,
                      &g_vT[(size_t)(bh * 64 + row) * 2048 + kn + c4]);
            }
            if (tid < 16) cpa16(uM + (uint32_t)(cur * 64 + (tid << 2)) * 4,
                                &mask[b * 2048 + kn + (tid << 2)]);
        }
        CP_COMMIT();
        CP_WAIT1();
        __syncthreads();
    }

    // ---- denominator: reduce across the 4 cq lanes only ----
    rs_lo += __shfl_xor_sync(0xffffffffu, rs_lo, 1);
    rs_lo += __shfl_xor_sync(0xffffffffu, rs_lo, 2);
    rs_hi += __shfl_xor_sync(0xffffffffu, rs_hi, 1);
    rs_hi += __shfl_xor_sync(0xffffffffu, rs_hi, 2);
    const float inv_lo = 1.0f / (rs_lo + 1e-8f);
    const float inv_hi = 1.0f / (rs_hi + 1e-8f);

    const int q_lo = q0 + qw + g;
    #pragma unroll
    for (int nt = 0; nt < 8; nt++) {
        const int dv = (nt << 3) + (cq << 1);
        *(float2*)&out[(size_t)((b * 2048 + q_lo) * 16 + h) * 64 + dv] =
            make_float2(acc[nt][0] * inv_lo, acc[nt][1] * inv_lo);
        *(float2*)&out[(size_t)((b * 2048 + q_lo + 8) * 16 + h) * 64 + dv] =
            make_float2(acc[nt][2] * inv_hi, acc[nt][3] * inv_hi);
    }
}

// ---------------------------------------------------------------------------
extern "C" void kernel_launch(void* const* d_in, const int* in_sizes, int n_in,
                              void* d_out, int out_size)
{
    const float* Q    = (const float*)d_in[0];
    const float* mask = (const float*)d_in[1];
    const float* Wq   = (const float*)d_in[2];
    const float* bq   = (const float*)d_in[3];
    const float* Wk   = (const float*)d_in[4];
    const float* bk   = (const float*)d_in[5];
    const float* Wv   = (const float*)d_in[6];
    const float* bv   = (const float*)d_in[7];
    float* out = (float*)d_out;

    cudaFuncSetAttribute(attn_kernel,
                         cudaFuncAttributeMaxDynamicSharedMemorySize,
                         ATTN_SMEM_FLOATS * (int)sizeof(float));

    proj_kernel<<<dim3(16, 32, 3), 256>>>(Q, Wq, bq, Wk, bk, Wv, bv);
    attn_kernel<<<dim3(16, 32), 256, ATTN_SMEM_FLOATS * sizeof(float)>>>(mask, out);
}

// round 6
// speedup vs baseline: 3.7811x; 1.1019x over previous
#include <cuda_runtime.h>
#include <cstdint>

// Shapes: Q[2,2048,1024], mask[2,2048], W_*[1024,1024], b_*[1024], out[2,2048,1024] fp32
// Scratch (stored PRE-ROUNDED to tf32 by proj epilogue):
//   g_q, g_k : [bh][s][64]            (A row-major / B col-major for QK^T)
//   g_vT     : [bh][64(dv)][2048(s)]  (B col-major for P@V)
__device__ float g_q [2 * 16 * 2048 * 64];
__device__ float g_k [2 * 16 * 2048 * 64];
__device__ float g_vT[2 * 16 * 64 * 2048];

// ---------------------------------------------------------------------------
// helpers
// ---------------------------------------------------------------------------
__device__ __forceinline__ float tf32r(float x) {
    uint32_t u;
    asm("cvt.rna.tf32.f32 %0, %1;" : "=r"(u) : "f"(x));
    return __uint_as_float(u);
}
__device__ __forceinline__ uint32_t fu(float x) { return __float_as_uint(x); }
__device__ __forceinline__ uint32_t smem_u32(const void* p) {
    uint32_t a;
    asm("{ .reg .u64 t; cvta.to.shared.u64 t, %1; cvt.u32.u64 %0, t; }" : "=r"(a) : "l"(p));
    return a;
}
__device__ __forceinline__ void ldsm4(uint32_t* r, uint32_t addr) {
    asm volatile("ldmatrix.sync.aligned.m8n8.x4.shared.b16 {%0,%1,%2,%3}, [%4];"
                 : "=r"(r[0]), "=r"(r[1]), "=r"(r[2]), "=r"(r[3]) : "r"(addr));
}
__device__ __forceinline__ void mma8(float* c, const uint32_t* a, const uint32_t* b) {
    asm volatile(
        "mma.sync.aligned.m16n8k8.row.col.f32.tf32.tf32.f32 "
        "{%0,%1,%2,%3}, {%4,%5,%6,%7}, {%8,%9}, {%0,%1,%2,%3};"
        : "+f"(c[0]), "+f"(c[1]), "+f"(c[2]), "+f"(c[3])
        : "r"(a[0]), "r"(a[1]), "r"(a[2]), "r"(a[3]), "r"(b[0]), "r"(b[1]));
}
__device__ __forceinline__ void cpa16(uint32_t dst, const void* src) {
    asm volatile("cp.async.ca.shared.global [%0], [%1], 16;" :: "r"(dst), "l"(src));
}
#define CP_COMMIT() asm volatile("cp.async.commit_group;" ::: "memory")
#define CP_WAIT1()  asm volatile("cp.async.wait_group 1;" ::: "memory")

// A-operand ldmatrix address (16-row tile at rowBase); stride in floats (mult of 4)
__device__ __forceinline__ uint32_t a_addr(const float* base, int rowBase, int stride, int lane) {
    const int row = rowBase + ((lane >> 3) & 1) * 8 + (lane & 7);
    const int col = (lane >> 4) << 2;
    return smem_u32(base + row * stride + col);
}
// B-pair ldmatrix address (two 8-row n-tiles at rowBase, rowBase+8)
__device__ __forceinline__ uint32_t b_addr(const float* base, int rowBase, int stride, int lane) {
    const int sel = lane >> 3;
    const int row = rowBase + (sel >> 1) * 8 + (lane & 7);
    const int col = (sel & 1) << 2;
    return smem_u32(base + row * stride + col);
}

// ---------------------------------------------------------------------------
// Projection GEMM v2: tile M=128 N=128, K-chunk 16, cp.async 2-stage.
// 256 thr (8 warps: 4m x 2n), warp tile 32m x 64n. rna rounding post-ldsm.
// grid = (8 n-tiles, 32 m-tiles, 3 proj)
// ---------------------------------------------------------------------------
#define PSTRIDE 20                         // floats per smem row (16 + 4 pad)
#define PSTG_FLOATS (256 * PSTRIDE)        // A rows 0-127, B rows 128-255

__global__ __launch_bounds__(256)
void proj_kernel(const float* __restrict__ A,
                 const float* __restrict__ Wq, const float* __restrict__ bq,
                 const float* __restrict__ Wk, const float* __restrict__ bk,
                 const float* __restrict__ Wv, const float* __restrict__ bv)
{
    __shared__ float sbuf[2][PSTG_FLOATS];
    __shared__ float s_bias[128];

    const int proj = blockIdx.z;
    const float* W    = (proj == 0) ? Wq : (proj == 1) ? Wk : Wv;
    const float* bias = (proj == 0) ? bq : (proj == 1) ? bk : bv;

    const int tid  = threadIdx.x;
    const int lane = tid & 31;
    const int w    = tid >> 5;
    const int g    = lane >> 2;
    const int cq   = lane & 3;
    const int mw   = (w & 3) << 5;       // warp m offset (0..96)
    const int nw   = (w >> 2) << 6;      // warp n offset (0 or 64)
    const int m0   = blockIdx.y << 7;
    const int n0   = blockIdx.x << 7;

    if (tid < 128) s_bias[tid] = bias[n0 + tid];

    const uint32_t uS  = smem_u32(sbuf);
    const uint32_t STG = PSTG_FLOATS * 4;

    const uint32_t aAdr0 = a_addr(&sbuf[0][0], mw,      PSTRIDE, lane);
    const uint32_t aAdr1 = a_addr(&sbuf[0][0], mw + 16, PSTRIDE, lane);
    uint32_t bAdr[4];
    #pragma unroll
    for (int j = 0; j < 4; j++)
        bAdr[j] = b_addr(&sbuf[0][128 * PSTRIDE], nw + 16 * j, PSTRIDE, lane);

    const int lrow = tid >> 2;           // 0..63
    const int lseg = (tid & 3) << 2;     // 0,4,8,12

    float acc[2][8][4] = {};

    // prefetch chunks 0,1
    #pragma unroll
    for (int st = 0; st < 2; st++) {
        const int k0 = st << 4;
        #pragma unroll
        for (int i = 0; i < 2; i++) {
            const int r = lrow + (i << 6);
            cpa16(uS + st * STG + (uint32_t)(r * PSTRIDE + lseg) * 4,
                  A + (size_t)(m0 + r) * 1024 + k0 + lseg);
            cpa16(uS + st * STG + (uint32_t)((128 + r) * PSTRIDE + lseg) * 4,
                  W + (size_t)(n0 + r) * 1024 + k0 + lseg);
        }
        CP_COMMIT();
    }

    for (int c = 0; c < 64; ++c) {
        const int st = c & 1;
        const uint32_t stoff = (uint32_t)st * STG;
        CP_WAIT1();
        __syncthreads();

        #pragma unroll
        for (int ks = 0; ks < 2; ++ks) {
            const uint32_t koff = stoff + (uint32_t)(ks << 5);
            uint32_t a0[4], a1[4];
            ldsm4(a0, aAdr0 + koff);
            ldsm4(a1, aAdr1 + koff);
            #pragma unroll
            for (int t = 0; t < 4; t++) {
                a0[t] = fu(tf32r(__uint_as_float(a0[t])));
                a1[t] = fu(tf32r(__uint_as_float(a1[t])));
            }
            #pragma unroll
            for (int j = 0; j < 4; j++) {
                uint32_t bb[4];
                ldsm4(bb, bAdr[j] + koff);
                #pragma unroll
                for (int t = 0; t < 4; t++) bb[t] = fu(tf32r(__uint_as_float(bb[t])));
                mma8(acc[0][2 * j],     a0, bb);
                mma8(acc[0][2 * j + 1], a0, bb + 2);
                mma8(acc[1][2 * j],     a1, bb);
                mma8(acc[1][2 * j + 1], a1, bb + 2);
            }
        }
        __syncthreads();

        if (c + 2 < 64) {
            const int k0 = (c + 2) << 4;
            #pragma unroll
            for (int i = 0; i < 2; i++) {
                const int r = lrow + (i << 6);
                cpa16(uS + stoff + (uint32_t)(r * PSTRIDE + lseg) * 4,
                      A + (size_t)(m0 + r) * 1024 + k0 + lseg);
                cpa16(uS + stoff + (uint32_t)((128 + r) * PSTRIDE + lseg) * 4,
                      W + (size_t)(n0 + r) * 1024 + k0 + lseg);
            }
        }
        CP_COMMIT();
    }

    // ---- epilogue (tf32-rounded stores) ----
    const int h = (n0 + nw) >> 6;
    #pragma unroll
    for (int mt = 0; mt < 2; mt++) {
        const int m  = m0 + mw + (mt << 4) + g;
        const int b_ = m >> 11;
        const int s  = m & 2047;
        const int bh = b_ * 16 + h;
        #pragma unroll
        for (int nt = 0; nt < 8; nt++) {
            const int col  = nw + (nt << 3) + (cq << 1);  // block-local n
            const int colh = col & 63;                     // within-head
            const float b0 = s_bias[col], b1 = s_bias[col + 1];
            if (proj < 2) {
                float* dst = (proj == 0) ? g_q : g_k;
                *(float2*)&dst[(size_t)(bh * 2048 + s) * 64 + colh] =
                    make_float2(tf32r(acc[mt][nt][0] + b0), tf32r(acc[mt][nt][1] + b1));
                *(float2*)&dst[(size_t)(bh * 2048 + s + 8) * 64 + colh] =
                    make_float2(tf32r(acc[mt][nt][2] + b0), tf32r(acc[mt][nt][3] + b1));
            } else {
                g_vT[(size_t)(bh * 64 + colh)     * 2048 + s]     = tf32r(acc[mt][nt][0] + b0);
                g_vT[(size_t)(bh * 64 + colh + 1) * 2048 + s]     = tf32r(acc[mt][nt][1] + b1);
                g_vT[(size_t)(bh * 64 + colh)     * 2048 + s + 8] = tf32r(acc[mt][nt][2] + b0);
                g_vT[(size_t)(bh * 64 + colh + 1) * 2048 + s + 8] = tf32r(acc[mt][nt][3] + b1);
            }
        }
    }
}

// ---------------------------------------------------------------------------
// Attention v4: 128 thr (4 warps), block tile = 128 q; warp tile = 32 q x 64 keys.
// S in regs, PV A-fragments via shuffle transpose, cp.async double-buffered K/V.
// ---------------------------------------------------------------------------
#define KV_STAGE  (64 * 68)
#define ATTN_SMEM_FLOATS (128 * 68 + 4 * KV_STAGE + 2 * 64)

__global__ __launch_bounds__(128, 2)
void attn_kernel(const float* __restrict__ mask, float* __restrict__ out)
{
    extern __shared__ float sm[];
    float* Qs    = sm;                       // [128 q][68]
    float* Ksm   = Qs + 128 * 68;            // [2][64 key][68]
    float* Vsm   = Ksm + 2 * KV_STAGE;       // [2][64 dv ][68]
    float* maskS = Vsm + 2 * KV_STAGE;       // [2][64]

    const int tid  = threadIdx.x;
    const int lane = tid & 31;
    const int w    = tid >> 5;               // 0..3
    const int g    = lane >> 2;
    const int cq   = lane & 3;
    const int qw   = w << 5;                 // warp q offset (0,32,64,96)
    const int q0   = blockIdx.x << 7;        // 128-q block
    const int bh   = blockIdx.y;
    const int b    = bh >> 4;
    const int h    = bh & 15;

    const uint32_t uQ = smem_u32(Qs);
    const uint32_t uK = smem_u32(Ksm);
    const uint32_t uV = smem_u32(Vsm);
    const uint32_t uM = smem_u32(maskS);

    const uint32_t qAdr0 = a_addr(Qs, qw,      68, lane);
    const uint32_t qAdr1 = a_addr(Qs, qw + 16, 68, lane);
    uint32_t kAdr[4], vAdr[4];
    #pragma unroll
    for (int j = 0; j < 4; j++) {
        kAdr[j] = b_addr(Ksm, 16 * j, 68, lane);
        vAdr[j] = b_addr(Vsm, 16 * j, 68, lane);
    }

    const int row8 = tid >> 4;               // 0..7
    const int c4   = (tid & 15) << 2;

    // ---- preload: Q (16 passes) + K/V tiles 0,1 ----
    #pragma unroll
    for (int i = 0; i < 16; i++) {
        const int row = row8 + (i << 3);
        cpa16(uQ + (uint32_t)(row * 68 + c4) * 4,
              &g_q[(size_t)(bh * 2048 + q0 + row) * 64 + c4]);
    }
    #pragma unroll
    for (int i = 0; i < 8; i++) {
        const int row = row8 + (i << 3);
        cpa16(uK + (uint32_t)(row * 68 + c4) * 4,
              &g_k[(size_t)(bh * 2048 + row) * 64 + c4]);
        cpa16(uV + (uint32_t)(row * 68 + c4) * 4,
              &g_vT[(size_t)(bh * 64 + row) * 2048 + c4]);
    }
    if (tid < 16) cpa16(uM + (uint32_t)(tid << 2) * 4, &mask[b * 2048 + (tid << 2)]);
    CP_COMMIT();
    #pragma unroll
    for (int i = 0; i < 8; i++) {
        const int row = row8 + (i << 3);
        cpa16(uK + (uint32_t)(KV_STAGE + row * 68 + c4) * 4,
              &g_k[(size_t)(bh * 2048 + 64 + row) * 64 + c4]);
        cpa16(uV + (uint32_t)(KV_STAGE + row * 68 + c4) * 4,
              &g_vT[(size_t)(bh * 64 + row) * 2048 + 64 + c4]);
    }
    if (tid < 16) cpa16(uM + (uint32_t)(64 + (tid << 2)) * 4, &mask[b * 2048 + 64 + (tid << 2)]);
    CP_COMMIT();
    CP_WAIT1();
    __syncthreads();

    float acc[16][4] = {};                   // [mt*8+nt][4]
    float rs[4] = {};                        // rows g, g+8 (mt0); g+16.., g+24.. (mt1)
    const uint32_t srcA = (uint32_t)((lane & ~3) | (cq >> 1));
    const uint32_t srcB = srcA + 2;
    const bool odd = cq & 1;

    for (int kt = 0; kt < 32; kt++) {
        const int cur = kt & 1;
        const uint32_t stoff = (uint32_t)(cur * KV_STAGE) * 4;

        // ---- S = Q K^T : 32q x 64 keys per warp ----
        float s[16][4] = {};
        #pragma unroll
        for (int ks = 0; ks < 8; ks++) {
            const uint32_t koff = (uint32_t)(ks << 5);
            uint32_t a0[4], a1[4];
            ldsm4(a0, qAdr0 + koff);
            ldsm4(a1, qAdr1 + koff);
            #pragma unroll
            for (int j = 0; j < 4; j++) {
                uint32_t bb[4];
                ldsm4(bb, kAdr[j] + stoff + koff);
                mma8(s[2 * j],         a0, bb);
                mma8(s[2 * j + 1],     a0, bb + 2);
                mma8(s[8 + 2 * j],     a1, bb);
                mma8(s[8 + 2 * j + 1], a1, bb + 2);
            }
        }

        // ---- P = exp(S/8)*mask (in regs), row sums ----
        #pragma unroll
        for (int mt = 0; mt < 2; mt++) {
            #pragma unroll
            for (int nt = 0; nt < 8; nt++) {
                const int idx = mt * 8 + nt;
                const int col = (nt << 3) + (cq << 1);
                const float2 mm = *(const float2*)&maskS[cur * 64 + col];
                const float p00 = __expf(s[idx][0] * 0.125f) * mm.x;
                const float p01 = __expf(s[idx][1] * 0.125f) * mm.y;
                const float p10 = __expf(s[idx][2] * 0.125f) * mm.x;
                const float p11 = __expf(s[idx][3] * 0.125f) * mm.y;
                rs[mt * 2 + 0] += p00 + p01;
                rs[mt * 2 + 1] += p10 + p11;
                s[idx][0] = p00; s[idx][1] = p01; s[idx][2] = p10; s[idx][3] = p11;
            }
        }

        // ---- acc += P @ V : A-fragments via register shuffle transpose ----
        #pragma unroll
        for (int ks = 0; ks < 8; ks++) {
            uint32_t a0[4], a1[4];
            #pragma unroll
            for (int mt = 0; mt < 2; mt++) {
                const int idx = mt * 8 + ks;
                const float x0 = __shfl_sync(0xffffffffu, s[idx][0], srcA);
                const float x1 = __shfl_sync(0xffffffffu, s[idx][1], srcA);
                const float y0 = __shfl_sync(0xffffffffu, s[idx][2], srcA);
                const float y1 = __shfl_sync(0xffffffffu, s[idx][3], srcA);
                const float z0 = __shfl_sync(0xffffffffu, s[idx][0], srcB);
                const float z1 = __shfl_sync(0xffffffffu, s[idx][1], srcB);
                const float w0 = __shfl_sync(0xffffffffu, s[idx][2], srcB);
                const float w1 = __shfl_sync(0xffffffffu, s[idx][3], srcB);
                uint32_t* a = mt ? a1 : a0;
                a[0] = fu(tf32r(odd ? x1 : x0));
                a[1] = fu(tf32r(odd ? y1 : y0));
                a[2] = fu(tf32r(odd ? z1 : z0));
                a[3] = fu(tf32r(odd ? w1 : w0));
            }
            const uint32_t koff = (uint32_t)(ks << 5);
            #pragma unroll
            for (int j = 0; j < 4; j++) {
                uint32_t bb[4];
                ldsm4(bb, vAdr[j] + stoff + koff);
                mma8(acc[2 * j],         a0, bb);
                mma8(acc[2 * j + 1],     a0, bb + 2);
                mma8(acc[8 + 2 * j],     a1, bb);
                mma8(acc[8 + 2 * j + 1], a1, bb + 2);
            }
        }

        // ---- pipeline: refill this stage with tile kt+2 ----
        __syncthreads();
        if (kt + 2 < 32) {
            const int kn = (kt + 2) << 6;
            #pragma unroll
            for (int i = 0; i < 8; i++) {
                const int row = row8 + (i << 3);
                cpa16(uK + stoff + (uint32_t)(row * 68 + c4) * 4,
                      &g_k[(size_t)(bh * 2048 + kn + row) * 64 + c4]);
                cpa16(uV + stoff + (uint32_t)(row * 68 + c4) * 4,
                      &g_vT[(size_t)(bh * 64 + row) * 2048 + kn + c4]);
            }
            if (tid < 16) cpa16(uM + (uint32_t)(cur * 64 + (tid << 2)) * 4,
                                &mask[b * 2048 + kn + (tid << 2)]);
        }
        CP_COMMIT();
        CP_WAIT1();
        __syncthreads();
    }

    // ---- denominator: reduce across the 4 cq lanes ----
    #pragma unroll
    for (int i = 0; i < 4; i++) {
        rs[i] += __shfl_xor_sync(0xffffffffu, rs[i], 1);
        rs[i] += __shfl_xor_sync(0xffffffffu, rs[i], 2);
        rs[i] = 1.0f / (rs[i] + 1e-8f);
    }

    #pragma unroll
    for (int mt = 0; mt < 2; mt++) {
        const int q_lo = q0 + qw + (mt << 4) + g;
        #pragma unroll
        for (int nt = 0; nt < 8; nt++) {
            const int idx = mt * 8 + nt;
            const int dv = (nt << 3) + (cq << 1);
            *(float2*)&out[(size_t)((b * 2048 + q_lo) * 16 + h) * 64 + dv] =
                make_float2(acc[idx][0] * rs[mt * 2], acc[idx][1] * rs[mt * 2]);
            *(float2*)&out[(size_t)((b * 2048 + q_lo + 8) * 16 + h) * 64 + dv] =
                make_float2(acc[idx][2] * rs[mt * 2 + 1], acc[idx][3] * rs[mt * 2 + 1]);
        }
    }
}

// ---------------------------------------------------------------------------
extern "C" void kernel_launch(void* const* d_in, const int* in_sizes, int n_in,
                              void* d_out, int out_size)
{
    const float* Q    = (const float*)d_in[0];
    const float* mask = (const float*)d_in[1];
    const float* Wq   = (const float*)d_in[2];
    const float* bq   = (const float*)d_in[3];
    const float* Wk   = (const float*)d_in[4];
    const float* bk   = (const float*)d_in[5];
    const float* Wv   = (const float*)d_in[6];
    const float* bv   = (const float*)d_in[7];
    float* out = (float*)d_out;

    cudaFuncSetAttribute(attn_kernel,
                         cudaFuncAttributeMaxDynamicSharedMemorySize,
                         ATTN_SMEM_FLOATS * (int)sizeof(float));

    proj_kernel<<<dim3(8, 32, 3), 256>>>(Q, Wq, bq, Wk, bk, Wv, bv);
    attn_kernel<<<dim3(16, 32), 128, ATTN_SMEM_FLOATS * sizeof(float)>>>(mask, out);
}

// round 7
// speedup vs baseline: 3.9329x; 1.0401x over previous
#include <cuda_runtime.h>
#include <cstdint>

// Shapes: Q[2,2048,1024], mask[2,2048], W_*[1024,1024], b_*[1024], out[2,2048,1024] fp32
// Scratch (all tf32-pre-rounded):
//   g_q, g_k : [bh][s][64]            (A row-major / B col-major for QK^T)
//   g_vT     : [bh][64(dv)][2048(s)]  (B col-major for P@V)
//   g_Ar     : rounded Q input; g_Wr : rounded W_Q/W_K/W_V
__device__ float g_q [2 * 16 * 2048 * 64];
__device__ float g_k [2 * 16 * 2048 * 64];
__device__ float g_vT[2 * 16 * 64 * 2048];
__device__ float g_Ar[4096 * 1024];
__device__ float g_Wr[3][1024 * 1024];

// ---------------------------------------------------------------------------
// helpers
// ---------------------------------------------------------------------------
__device__ __forceinline__ float tf32r(float x) {
    uint32_t u;
    asm("cvt.rna.tf32.f32 %0, %1;" : "=r"(u) : "f"(x));
    return __uint_as_float(u);
}
__device__ __forceinline__ uint32_t fu(float x) { return __float_as_uint(x); }
__device__ __forceinline__ uint32_t smem_u32(const void* p) {
    uint32_t a;
    asm("{ .reg .u64 t; cvta.to.shared.u64 t, %1; cvt.u32.u64 %0, t; }" : "=r"(a) : "l"(p));
    return a;
}
__device__ __forceinline__ void ldsm4(uint32_t* r, uint32_t addr) {
    asm volatile("ldmatrix.sync.aligned.m8n8.x4.shared.b16 {%0,%1,%2,%3}, [%4];"
                 : "=r"(r[0]), "=r"(r[1]), "=r"(r[2]), "=r"(r[3]) : "r"(addr));
}
__device__ __forceinline__ void mma8(float* c, const uint32_t* a, const uint32_t* b) {
    asm volatile(
        "mma.sync.aligned.m16n8k8.row.col.f32.tf32.tf32.f32 "
        "{%0,%1,%2,%3}, {%4,%5,%6,%7}, {%8,%9}, {%0,%1,%2,%3};"
        : "+f"(c[0]), "+f"(c[1]), "+f"(c[2]), "+f"(c[3])
        : "r"(a[0]), "r"(a[1]), "r"(a[2]), "r"(a[3]), "r"(b[0]), "r"(b[1]));
}
__device__ __forceinline__ void mma8u(float* c, uint32_t a0, uint32_t a1,
                                      uint32_t a2, uint32_t a3, const uint32_t* b) {
    asm volatile(
        "mma.sync.aligned.m16n8k8.row.col.f32.tf32.tf32.f32 "
        "{%0,%1,%2,%3}, {%4,%5,%6,%7}, {%8,%9}, {%0,%1,%2,%3};"
        : "+f"(c[0]), "+f"(c[1]), "+f"(c[2]), "+f"(c[3])
        : "r"(a0), "r"(a1), "r"(a2), "r"(a3), "r"(b[0]), "r"(b[1]));
}
__device__ __forceinline__ void cpa16(uint32_t dst, const void* src) {
    asm volatile("cp.async.ca.shared.global [%0], [%1], 16;" :: "r"(dst), "l"(src));
}
#define CP_COMMIT() asm volatile("cp.async.commit_group;" ::: "memory")
#define CP_WAIT1()  asm volatile("cp.async.wait_group 1;" ::: "memory")

// A-operand ldmatrix address (16-row tile at rowBase)
__device__ __forceinline__ uint32_t a_addr(const float* base, int rowBase, int stride, int lane) {
    const int row = rowBase + ((lane >> 3) & 1) * 8 + (lane & 7);
    const int col = (lane >> 4) << 2;
    return smem_u32(base + row * stride + col);
}
// B-pair ldmatrix address (two 8-row n-tiles at rowBase, rowBase+8)
__device__ __forceinline__ uint32_t b_addr(const float* base, int rowBase, int stride, int lane) {
    const int sel = lane >> 3;
    const int row = rowBase + (sel >> 1) * 8 + (lane & 7);
    const int col = (sel & 1) << 2;
    return smem_u32(base + row * stride + col);
}

// ---------------------------------------------------------------------------
// tf32 pre-round pass: y==0 -> Q input (1M float4); y in 1..3 -> W matrices (256K f4)
// ---------------------------------------------------------------------------
__global__ __launch_bounds__(256)
void round_kernel(const float* __restrict__ Qin,
                  const float* __restrict__ Wq,
                  const float* __restrict__ Wk,
                  const float* __restrict__ Wv)
{
    const int i = blockIdx.x * 256 + threadIdx.x;
    const int y = blockIdx.y;
    const float* src;
    float* dst;
    if (y == 0)      { src = Qin; dst = g_Ar; }
    else             { src = (y == 1) ? Wq : (y == 2) ? Wk : Wv; dst = g_Wr[y - 1];
                       if (i >= 262144) return; }
    const float4 v = ((const float4*)src)[i];
    ((float4*)dst)[i] = make_float4(tf32r(v.x), tf32r(v.y), tf32r(v.z), tf32r(v.w));
}

// ---------------------------------------------------------------------------
// Projection GEMM: tile M=128 N=128, K-chunk 16, cp.async 2-stage, no in-loop cvt.
// 256 thr (8 warps: 4m x 2n). grid = (8 n-tiles, 32 m-tiles, 3 proj)
// ---------------------------------------------------------------------------
#define PSTRIDE 20
#define PSTG_FLOATS (256 * PSTRIDE)

__global__ __launch_bounds__(256)
void proj_kernel(const float* __restrict__ bq,
                 const float* __restrict__ bk,
                 const float* __restrict__ bv)
{
    __shared__ float sbuf[2][PSTG_FLOATS];
    __shared__ float s_bias[128];

    const int proj = blockIdx.z;
    const float* A    = g_Ar;
    const float* W    = g_Wr[proj];
    const float* bias = (proj == 0) ? bq : (proj == 1) ? bk : bv;

    const int tid  = threadIdx.x;
    const int lane = tid & 31;
    const int w    = tid >> 5;
    const int g    = lane >> 2;
    const int cq   = lane & 3;
    const int mw   = (w & 3) << 5;
    const int nw   = (w >> 2) << 6;
    const int m0   = blockIdx.y << 7;
    const int n0   = blockIdx.x << 7;

    if (tid < 128) s_bias[tid] = bias[n0 + tid];

    const uint32_t uS  = smem_u32(sbuf);
    const uint32_t STG = PSTG_FLOATS * 4;

    const uint32_t aAdr0 = a_addr(&sbuf[0][0], mw,      PSTRIDE, lane);
    const uint32_t aAdr1 = a_addr(&sbuf[0][0], mw + 16, PSTRIDE, lane);
    uint32_t bAdr[4];
    #pragma unroll
    for (int j = 0; j < 4; j++)
        bAdr[j] = b_addr(&sbuf[0][128 * PSTRIDE], nw + 16 * j, PSTRIDE, lane);

    const int lrow = tid >> 2;
    const int lseg = (tid & 3) << 2;

    float acc[2][8][4] = {};

    #pragma unroll
    for (int st = 0; st < 2; st++) {
        const int k0 = st << 4;
        #pragma unroll
        for (int i = 0; i < 2; i++) {
            const int r = lrow + (i << 6);
            cpa16(uS + st * STG + (uint32_t)(r * PSTRIDE + lseg) * 4,
                  A + (size_t)(m0 + r) * 1024 + k0 + lseg);
            cpa16(uS + st * STG + (uint32_t)((128 + r) * PSTRIDE + lseg) * 4,
                  W + (size_t)(n0 + r) * 1024 + k0 + lseg);
        }
        CP_COMMIT();
    }

    for (int c = 0; c < 64; ++c) {
        const int st = c & 1;
        const uint32_t stoff = (uint32_t)st * STG;
        CP_WAIT1();
        __syncthreads();

        #pragma unroll
        for (int ks = 0; ks < 2; ++ks) {
            const uint32_t koff = stoff + (uint32_t)(ks << 5);
            uint32_t a0[4], a1[4];
            ldsm4(a0, aAdr0 + koff);
            ldsm4(a1, aAdr1 + koff);
            #pragma unroll
            for (int j = 0; j < 4; j++) {
                uint32_t bb[4];
                ldsm4(bb, bAdr[j] + koff);
                mma8(acc[0][2 * j],     a0, bb);
                mma8(acc[0][2 * j + 1], a0, bb + 2);
                mma8(acc[1][2 * j],     a1, bb);
                mma8(acc[1][2 * j + 1], a1, bb + 2);
            }
        }
        __syncthreads();

        if (c + 2 < 64) {
            const int k0 = (c + 2) << 4;
            #pragma unroll
            for (int i = 0; i < 2; i++) {
                const int r = lrow + (i << 6);
                cpa16(uS + stoff + (uint32_t)(r * PSTRIDE + lseg) * 4,
                      A + (size_t)(m0 + r) * 1024 + k0 + lseg);
                cpa16(uS + stoff + (uint32_t)((128 + r) * PSTRIDE + lseg) * 4,
                      W + (size_t)(n0 + r) * 1024 + k0 + lseg);
            }
        }
        CP_COMMIT();
    }

    // ---- epilogue (tf32-rounded stores) ----
    const int h = (n0 + nw) >> 6;
    #pragma unroll
    for (int mt = 0; mt < 2; mt++) {
        const int m  = m0 + mw + (mt << 4) + g;
        const int b_ = m >> 11;
        const int s  = m & 2047;
        const int bh = b_ * 16 + h;
        #pragma unroll
        for (int nt = 0; nt < 8; nt++) {
            const int col  = nw + (nt << 3) + (cq << 1);
            const int colh = col & 63;
            const float b0 = s_bias[col], b1 = s_bias[col + 1];
            if (proj < 2) {
                float* dst = (proj == 0) ? g_q : g_k;
                *(float2*)&dst[(size_t)(bh * 2048 + s) * 64 + colh] =
                    make_float2(tf32r(acc[mt][nt][0] + b0), tf32r(acc[mt][nt][1] + b1));
                *(float2*)&dst[(size_t)(bh * 2048 + s + 8) * 64 + colh] =
                    make_float2(tf32r(acc[mt][nt][2] + b0), tf32r(acc[mt][nt][3] + b1));
            } else {
                g_vT[(size_t)(bh * 64 + colh)     * 2048 + s]     = tf32r(acc[mt][nt][0] + b0);
                g_vT[(size_t)(bh * 64 + colh + 1) * 2048 + s]     = tf32r(acc[mt][nt][1] + b1);
                g_vT[(size_t)(bh * 64 + colh)     * 2048 + s + 8] = tf32r(acc[mt][nt][2] + b0);
                g_vT[(size_t)(bh * 64 + colh + 1) * 2048 + s + 8] = tf32r(acc[mt][nt][3] + b1);
            }
        }
    }
}

// ---------------------------------------------------------------------------
// Attention v5: key-permuted K smem => PV A-fragment is a register rename of
// the exp'd S accumulator (NO shuffles). 128 thr, warp = 32q x 64 keys.
// Key k stored at smem row sigma(k) = ((k&3)<<1)|((k&7)>>2) within its 8-group;
// accumulator col 2c -> key c, col 2c+1 -> key c+4.
// ---------------------------------------------------------------------------
#define KV_STAGE  (64 * 68)
#define ATTN_SMEM_FLOATS (128 * 68 + 4 * KV_STAGE + 2 * 64)

__global__ __launch_bounds__(128, 2)
void attn_kernel(const float* __restrict__ mask, float* __restrict__ out)
{
    extern __shared__ float sm[];
    float* Qs    = sm;                       // [128 q][68]
    float* Ksm   = Qs + 128 * 68;            // [2][64 key(perm)][68]
    float* Vsm   = Ksm + 2 * KV_STAGE;       // [2][64 dv][68]
    float* maskS = Vsm + 2 * KV_STAGE;       // [2][64] natural order

    const int tid  = threadIdx.x;
    const int lane = tid & 31;
    const int w    = tid >> 5;
    const int g    = lane >> 2;
    const int cq   = lane & 3;
    const int qw   = w << 5;
    const int q0   = blockIdx.x << 7;
    const int bh   = blockIdx.y;
    const int b    = bh >> 4;
    const int h    = bh & 15;

    const uint32_t uQ = smem_u32(Qs);
    const uint32_t uK = smem_u32(Ksm);
    const uint32_t uV = smem_u32(Vsm);
    const uint32_t uM = smem_u32(maskS);

    const uint32_t qAdr0 = a_addr(Qs, qw,      68, lane);
    const uint32_t qAdr1 = a_addr(Qs, qw + 16, 68, lane);
    uint32_t kAdr[4], vAdr[4];
    #pragma unroll
    for (int j = 0; j < 4; j++) {
        kAdr[j] = b_addr(Ksm, 16 * j, 68, lane);
        vAdr[j] = b_addr(Vsm, 16 * j, 68, lane);
    }

    const int row8 = tid >> 4;
    const int c4   = (tid & 15) << 2;

    // ---- preload: Q + K/V tiles 0,1 (K rows permuted) ----
    #pragma unroll
    for (int i = 0; i < 16; i++) {
        const int row = row8 + (i << 3);
        cpa16(uQ + (uint32_t)(row * 68 + c4) * 4,
              &g_q[(size_t)(bh * 2048 + q0 + row) * 64 + c4]);
    }
    #pragma unroll
    for (int i = 0; i < 8; i++) {
        const int row = row8 + (i << 3);
        const int pr  = (row & ~7) | ((row & 3) << 1) | ((row >> 2) & 1);
        cpa16(uK + (uint32_t)(pr * 68 + c4) * 4,
              &g_k[(size_t)(bh * 2048 + row) * 64 + c4]);
        cpa16(uV + (uint32_t)(row * 68 + c4) * 4,
              &g_vT[(size_t)(bh * 64 + row) * 2048 + c4]);
    }
    if (tid < 16) cpa16(uM + (uint32_t)(tid << 2) * 4, &mask[b * 2048 + (tid << 2)]);
    CP_COMMIT();
    #pragma unroll
    for (int i = 0; i < 8; i++) {
        const int row = row8 + (i << 3);
        const int pr  = (row & ~7) | ((row & 3) << 1) | ((row >> 2) & 1);
        cpa16(uK + (uint32_t)(KV_STAGE + pr * 68 + c4) * 4,
              &g_k[(size_t)(bh * 2048 + 64 + row) * 64 + c4]);
        cpa16(uV + (uint32_t)(KV_STAGE + row * 68 + c4) * 4,
              &g_vT[(size_t)(bh * 64 + row) * 2048 + 64 + c4]);
    }
    if (tid < 16) cpa16(uM + (uint32_t)(64 + (tid << 2)) * 4, &mask[b * 2048 + 64 + (tid << 2)]);
    CP_COMMIT();
    CP_WAIT1();
    __syncthreads();

    float acc[16][4] = {};
    float rs[4] = {};

    for (int kt = 0; kt < 32; kt++) {
        const int cur = kt & 1;
        const uint32_t stoff = (uint32_t)(cur * KV_STAGE) * 4;

        // ---- S = Q K^T (keys arrive permuted in accumulator cols) ----
        float s[16][4] = {};
        #pragma unroll
        for (int ks = 0; ks < 8; ks++) {
            const uint32_t koff = (uint32_t)(ks << 5);
            uint32_t a0[4], a1[4];
            ldsm4(a0, qAdr0 + koff);
            ldsm4(a1, qAdr1 + koff);
            #pragma unroll
            for (int j = 0; j < 4; j++) {
                uint32_t bb[4];
                ldsm4(bb, kAdr[j] + stoff + koff);
                mma8(s[2 * j],         a0, bb);
                mma8(s[2 * j + 1],     a0, bb + 2);
                mma8(s[8 + 2 * j],     a1, bb);
                mma8(s[8 + 2 * j + 1], a1, bb + 2);
            }
        }

        // ---- mask values: col 2cq -> key nt*8+cq, col 2cq+1 -> key nt*8+cq+4 ----
        float mv0[8], mv1[8];
        #pragma unroll
        for (int nt = 0; nt < 8; nt++) {
            mv0[nt] = maskS[cur * 64 + (nt << 3) + cq];
            mv1[nt] = maskS[cur * 64 + (nt << 3) + cq + 4];
        }

        // ---- P = exp(S/8)*mask; unrounded row sums; tf32-rounded P in regs ----
        #pragma unroll
        for (int mt = 0; mt < 2; mt++) {
            #pragma unroll
            for (int nt = 0; nt < 8; nt++) {
                const int idx = mt * 8 + nt;
                const float p00 = __expf(s[idx][0] * 0.125f) * mv0[nt];
                const float p01 = __expf(s[idx][1] * 0.125f) * mv1[nt];
                const float p10 = __expf(s[idx][2] * 0.125f) * mv0[nt];
                const float p11 = __expf(s[idx][3] * 0.125f) * mv1[nt];
                rs[mt * 2 + 0] += p00 + p01;
                rs[mt * 2 + 1] += p10 + p11;
                s[idx][0] = tf32r(p00); s[idx][1] = tf32r(p01);
                s[idx][2] = tf32r(p10); s[idx][3] = tf32r(p11);
            }
        }

        // ---- acc += P @ V : A-fragment = register rename {d0,d2,d1,d3} ----
        #pragma unroll
        for (int ks = 0; ks < 8; ks++) {
            const uint32_t koff = (uint32_t)(ks << 5);
            const int i0 = ks, i1 = 8 + ks;
            #pragma unroll
            for (int j = 0; j < 4; j++) {
                uint32_t bb[4];
                ldsm4(bb, vAdr[j] + stoff + koff);
                mma8u(acc[2 * j],         fu(s[i0][0]), fu(s[i0][2]), fu(s[i0][1]), fu(s[i0][3]), bb);
                mma8u(acc[2 * j + 1],     fu(s[i0][0]), fu(s[i0][2]), fu(s[i0][1]), fu(s[i0][3]), bb + 2);
                mma8u(acc[8 + 2 * j],     fu(s[i1][0]), fu(s[i1][2]), fu(s[i1][1]), fu(s[i1][3]), bb);
                mma8u(acc[8 + 2 * j + 1], fu(s[i1][0]), fu(s[i1][2]), fu(s[i1][1]), fu(s[i1][3]), bb + 2);
            }
        }

        // ---- pipeline: refill this stage with tile kt+2 ----
        __syncthreads();
        if (kt + 2 < 32) {
            const int kn = (kt + 2) << 6;
            #pragma unroll
            for (int i = 0; i < 8; i++) {
                const int row = row8 + (i << 3);
                const int pr  = (row & ~7) | ((row & 3) << 1) | ((row >> 2) & 1);
                cpa16(uK + stoff + (uint32_t)(pr * 68 + c4) * 4,
                      &g_k[(size_t)(bh * 2048 + kn + row) * 64 + c4]);
                cpa16(uV + stoff + (uint32_t)(row * 68 + c4) * 4,
                      &g_vT[(size_t)(bh * 64 + row) * 2048 + kn + c4]);
            }
            if (tid < 16) cpa16(uM + (uint32_t)(cur * 64 + (tid << 2)) * 4,
                                &mask[b * 2048 + kn + (tid << 2)]);
        }
        CP_COMMIT();
        CP_WAIT1();
        __syncthreads();
    }

    // ---- denominator: reduce across the 4 cq lanes ----
    #pragma unroll
    for (int i = 0; i < 4; i++) {
        rs[i] += __shfl_xor_sync(0xffffffffu, rs[i], 1);
        rs[i] += __shfl_xor_sync(0xffffffffu, rs[i], 2);
        rs[i] = 1.0f / (rs[i] + 1e-8f);
    }

    #pragma unroll
    for (int mt = 0; mt < 2; mt++) {
        const int q_lo = q0 + qw + (mt << 4) + g;
        #pragma unroll
        for (int nt = 0; nt < 8; nt++) {
            const int idx = mt * 8 + nt;
            const int dv = (nt << 3) + (cq << 1);
            *(float2*)&out[(size_t)((b * 2048 + q_lo) * 16 + h) * 64 + dv] =
                make_float2(acc[idx][0] * rs[mt * 2], acc[idx][1] * rs[mt * 2]);
            *(float2*)&out[(size_t)((b * 2048 + q_lo + 8) * 16 + h) * 64 + dv] =
                make_float2(acc[idx][2] * rs[mt * 2 + 1], acc[idx][3] * rs[mt * 2 + 1]);
        }
    }
}

// ---------------------------------------------------------------------------
extern "C" void kernel_launch(void* const* d_in, const int* in_sizes, int n_in,
                              void* d_out, int out_size)
{
    const float* Q    = (const float*)d_in[0];
    const float* mask = (const float*)d_in[1];
    const float* Wq   = (const float*)d_in[2];
    const float* bq   = (const float*)d_in[3];
    const float* Wk   = (const float*)d_in[4];
    const float* bk   = (const float*)d_in[5];
    const float* Wv   = (const float*)d_in[6];
    const float* bv   = (const float*)d_in[7];
    float* out = (float*)d_out;

    cudaFuncSetAttribute(attn_kernel,
                         cudaFuncAttributeMaxDynamicSharedMemorySize,
                         ATTN_SMEM_FLOATS * (int)sizeof(float));

    round_kernel<<<dim3(4096, 4), 256>>>(Q, Wq, Wk, Wv);
    proj_kernel<<<dim3(8, 32, 3), 256>>>(bq, bk, bv);
    attn_kernel<<<dim3(16, 32), 128, ATTN_SMEM_FLOATS * sizeof(float)>>>(mask, out);
}

// round 8
// speedup vs baseline: 5.4032x; 1.3739x over previous
#include <cuda_runtime.h>
#include <cuda_fp16.h>
#include <cstdint>

// Shapes: Q[2,2048,1024], mask[2,2048], W_*[1024,1024], b_*[1024], out[2,2048,1024] fp32
// Scratch (fp16): g_qh,g_kh [bh][s][64]; g_vTh [bh][64(dv)][2048(s)];
//                 g_Ah = fp16 Q-input, g_Wh = fp16 weights
__device__ __align__(16) __half g_qh [2 * 16 * 2048 * 64];
__device__ __align__(16) __half g_kh [2 * 16 * 2048 * 64];
__device__ __align__(16) __half g_vTh[2 * 16 * 64 * 2048];
__device__ __align__(16) __half g_Ah [4096 * 1024];
__device__ __align__(16) __half g_Wh [3][1024 * 1024];

// ---------------------------------------------------------------------------
// helpers
// ---------------------------------------------------------------------------
__device__ __forceinline__ uint32_t packh(float lo, float hi) {
    uint32_t d;
    asm("cvt.rn.f16x2.f32 %0, %1, %2;" : "=r"(d) : "f"(hi), "f"(lo));
    return d;
}
__device__ __forceinline__ uint32_t smem_u32(const void* p) {
    uint32_t a;
    asm("{ .reg .u64 t; cvta.to.shared.u64 t, %1; cvt.u32.u64 %0, t; }" : "=r"(a) : "l"(p));
    return a;
}
__device__ __forceinline__ void ldsm4(uint32_t* r, uint32_t addr) {
    asm volatile("ldmatrix.sync.aligned.m8n8.x4.shared.b16 {%0,%1,%2,%3}, [%4];"
                 : "=r"(r[0]), "=r"(r[1]), "=r"(r[2]), "=r"(r[3]) : "r"(addr));
}
// D += A(m16k16,row,f16) * B(k16n8,col,f16), f32 accum
__device__ __forceinline__ void mma16(float* c, const uint32_t* a, const uint32_t* b) {
    asm volatile(
        "mma.sync.aligned.m16n8k16.row.col.f32.f16.f16.f32 "
        "{%0,%1,%2,%3}, {%4,%5,%6,%7}, {%8,%9}, {%0,%1,%2,%3};"
        : "+f"(c[0]), "+f"(c[1]), "+f"(c[2]), "+f"(c[3])
        : "r"(a[0]), "r"(a[1]), "r"(a[2]), "r"(a[3]), "r"(b[0]), "r"(b[1]));
}
__device__ __forceinline__ void cpa16(uint32_t dst, const void* src) {
    asm volatile("cp.async.ca.shared.global [%0], [%1], 16;" :: "r"(dst), "l"(src));
}
#define CP_COMMIT() asm volatile("cp.async.commit_group;" ::: "memory")
#define CP_WAIT1()  asm volatile("cp.async.wait_group 1;" ::: "memory")

// A-operand ldmatrix byte address (16-row x k16 tile): m0=r0-7/k0-7, m1=r8-15/k0-7,
// m2=r0-7/k8-15, m3=r8-15/k8-15  -> regs a0..a3 of the fp16 m16n8k16 A fragment.
__device__ __forceinline__ uint32_t a_addr_h(const __half* base, int rowBase, int stride, int lane) {
    const int row = rowBase + ((lane >> 3) & 1) * 8 + (lane & 7);
    const int col = (lane >> 4) << 3;
    return smem_u32(base + row * stride + col);
}
// B-pair: m0=n0-7/k0-7, m1=n0-7/k8-15, m2=n8-15/k0-7, m3=n8-15/k8-15
// -> {r0,r1} = B frag n-group0, {r2,r3} = n-group1.
__device__ __forceinline__ uint32_t b_addr_h(const __half* base, int rowBase, int stride, int lane) {
    const int sel = lane >> 3;
    const int row = rowBase + (sel >> 1) * 8 + (lane & 7);
    const int col = (sel & 1) << 3;
    return smem_u32(base + row * stride + col);
}

// ---------------------------------------------------------------------------
// fp16 pre-convert: y==0 -> Q input (1M float4); y in 1..3 -> W (256K float4)
// ---------------------------------------------------------------------------
__global__ __launch_bounds__(256)
void round_kernel(const float* __restrict__ Qin,
                  const float* __restrict__ Wq,
                  const float* __restrict__ Wk,
                  const float* __restrict__ Wv)
{
    const int i = blockIdx.x * 256 + threadIdx.x;
    const int y = blockIdx.y;
    const float* src;
    __half* dst;
    if (y == 0) { src = Qin; dst = g_Ah; }
    else        { if (i >= 262144) return;
                  src = (y == 1) ? Wq : (y == 2) ? Wk : Wv; dst = g_Wh[y - 1]; }
    const float4 v = ((const float4*)src)[i];
    ((uint2*)dst)[i] = make_uint2(packh(v.x, v.y), packh(v.z, v.w));
}

// ---------------------------------------------------------------------------
// Projection GEMM (fp16 mma): tile M=128 N=128, K-chunk 32 (2 k16 steps),
// cp.async 2-stage. 256 thr (8 warps: 4m x 2n). grid = (8, 32, 3).
// ---------------------------------------------------------------------------
#define PSTR 40                      // halves per smem row (32 + 8 pad)
#define PSTG_B (256 * PSTR * 2)      // bytes per stage

__global__ __launch_bounds__(256)
void proj_kernel(const float* __restrict__ bq,
                 const float* __restrict__ bk,
                 const float* __restrict__ bv)
{
    __shared__ __align__(16) __half sbuf[2][256 * PSTR];
    __shared__ float s_bias[128];

    const int proj = blockIdx.z;
    const __half* A = g_Ah;
    const __half* W = g_Wh[proj];
    const float* bias = (proj == 0) ? bq : (proj == 1) ? bk : bv;

    const int tid  = threadIdx.x;
    const int lane = tid & 31;
    const int w    = tid >> 5;
    const int g    = lane >> 2;
    const int cq   = lane & 3;
    const int mw   = (w & 3) << 5;
    const int nw   = (w >> 2) << 6;
    const int m0   = blockIdx.y << 7;
    const int n0   = blockIdx.x << 7;

    if (tid < 128) s_bias[tid] = bias[n0 + tid];

    const uint32_t uS = smem_u32(sbuf);

    const uint32_t aAdr0 = a_addr_h(&sbuf[0][0], mw,      PSTR, lane);
    const uint32_t aAdr1 = a_addr_h(&sbuf[0][0], mw + 16, PSTR, lane);
    uint32_t bAdr[4];
    #pragma unroll
    for (int j = 0; j < 4; j++)
        bAdr[j] = b_addr_h(&sbuf[0][128 * PSTR], nw + 16 * j, PSTR, lane);

    // loader: thread = one row (A rows 0-127, W rows 128-255), 4x16B per stage
    const __half* srcbase = (tid < 128) ? (A + (size_t)(m0 + tid) * 1024)
                                        : (W + (size_t)(n0 + tid - 128) * 1024);
    const uint32_t drow = uS + (uint32_t)(tid * PSTR) * 2;

    float acc[2][8][4] = {};

    #pragma unroll
    for (int st = 0; st < 2; st++) {
        const int k0 = st << 5;
        #pragma unroll
        for (int i = 0; i < 4; i++)
            cpa16(drow + st * PSTG_B + i * 16, srcbase + k0 + i * 8);
        CP_COMMIT();
    }

    for (int c = 0; c < 32; ++c) {
        const int st = c & 1;
        const uint32_t stoff = (uint32_t)st * PSTG_B;
        CP_WAIT1();
        __syncthreads();

        #pragma unroll
        for (int ks = 0; ks < 2; ++ks) {
            const uint32_t koff = stoff + (uint32_t)(ks << 5);   // 16 halves = 32B
            uint32_t a0[4], a1[4];
            ldsm4(a0, aAdr0 + koff);
            ldsm4(a1, aAdr1 + koff);
            #pragma unroll
            for (int j = 0; j < 4; j++) {
                uint32_t bb[4];
                ldsm4(bb, bAdr[j] + koff);
                mma16(acc[0][2 * j],     a0, bb);
                mma16(acc[0][2 * j + 1], a0, bb + 2);
                mma16(acc[1][2 * j],     a1, bb);
                mma16(acc[1][2 * j + 1], a1, bb + 2);
            }
        }
        __syncthreads();

        if (c + 2 < 32) {
            const int k0 = (c + 2) << 5;
            #pragma unroll
            for (int i = 0; i < 4; i++)
                cpa16(drow + stoff + i * 16, srcbase + k0 + i * 8);
        }
        CP_COMMIT();
    }

    // ---- epilogue (fp16 stores; fp16 round == tf32 round for these mantissas) ----
    const int h = (n0 + nw) >> 6;
    #pragma unroll
    for (int mt = 0; mt < 2; mt++) {
        const int m  = m0 + mw + (mt << 4) + g;
        const int b_ = m >> 11;
        const int s  = m & 2047;
        const int bh = b_ * 16 + h;
        #pragma unroll
        for (int nt = 0; nt < 8; nt++) {
            const int col  = nw + (nt << 3) + (cq << 1);
            const int colh = col & 63;
            const float b0 = s_bias[col], b1 = s_bias[col + 1];
            if (proj < 2) {
                __half* dst = (proj == 0) ? g_qh : g_kh;
                *(uint32_t*)&dst[(size_t)(bh * 2048 + s) * 64 + colh] =
                    packh(acc[mt][nt][0] + b0, acc[mt][nt][1] + b1);
                *(uint32_t*)&dst[(size_t)(bh * 2048 + s + 8) * 64 + colh] =
                    packh(acc[mt][nt][2] + b0, acc[mt][nt][3] + b1);
            } else {
                g_vTh[(size_t)(bh * 64 + colh)     * 2048 + s]     = __float2half_rn(acc[mt][nt][0] + b0);
                g_vTh[(size_t)(bh * 64 + colh + 1) * 2048 + s]     = __float2half_rn(acc[mt][nt][1] + b1);
                g_vTh[(size_t)(bh * 64 + colh)     * 2048 + s + 8] = __float2half_rn(acc[mt][nt][2] + b0);
                g_vTh[(size_t)(bh * 64 + colh + 1) * 2048 + s + 8] = __float2half_rn(acc[mt][nt][3] + b1);
            }
        }
    }
}

// ---------------------------------------------------------------------------
// Attention v6 (fp16 m16n8k16): 128 thr, warp = 32q x 64 keys.
// Q fragments cached in regs for all 32 kt. PV A-fragments = f16x2 packs of
// the exp'd S accumulator (pairing matches natively — no transpose at all).
// ---------------------------------------------------------------------------
#define HSTR 72                         // halves per smem row (64 + 8 pad)
#define KSTG_B (64 * HSTR * 2)          // bytes per K or V stage
#define ATTN_SMEM_BYTES (128 * HSTR * 2 + 4 * KSTG_B + 2 * 64 * 4)

__global__ __launch_bounds__(128, 2)
void attn_kernel(const float* __restrict__ mask, float* __restrict__ out)
{
    extern __shared__ __align__(16) __half smh[];
    __half* Qs = smh;                        // [128 q][72]
    __half* Ks = smh + 128 * HSTR;           // [2][64 key][72]
    __half* Vs = Ks + 2 * 64 * HSTR;         // [2][64 dv][72]
    float* maskS = (float*)(Vs + 2 * 64 * HSTR);   // [2][64]

    const int tid  = threadIdx.x;
    const int lane = tid & 31;
    const int w    = tid >> 5;
    const int g    = lane >> 2;
    const int cq   = lane & 3;
    const int qw   = w << 5;
    const int q0   = blockIdx.x << 7;
    const int bh   = blockIdx.y;
    const int b    = bh >> 4;
    const int h    = bh & 15;

    const uint32_t uQ = smem_u32(Qs);
    const uint32_t uK = smem_u32(Ks);
    const uint32_t uV = smem_u32(Vs);
    const uint32_t uM = smem_u32(maskS);

    uint32_t kAdr[4], vAdr[4];
    #pragma unroll
    for (int j = 0; j < 4; j++) {
        kAdr[j] = b_addr_h(Ks, 16 * j, HSTR, lane);
        vAdr[j] = b_addr_h(Vs, 16 * j, HSTR, lane);
    }

    const int r2 = tid >> 1;             // 0..63
    const int sB = (tid & 1) * 64;       // byte offset in 128B row

    // ---- preload: Q (all 128 rows) + K/V tiles 0,1 + mask ----
    #pragma unroll
    for (int i = 0; i < 8; i++)
        cpa16(uQ + (uint32_t)(tid * HSTR) * 2 + i * 16,
              g_qh + (size_t)(bh * 2048 + q0 + tid) * 64 + i * 8);
    #pragma unroll
    for (int i = 0; i < 4; i++) {
        cpa16(uK + (uint32_t)(r2 * HSTR) * 2 + sB + i * 16,
              g_kh + (size_t)(bh * 2048 + r2) * 64 + (sB >> 1) + i * 8);
        cpa16(uV + (uint32_t)(r2 * HSTR) * 2 + sB + i * 16,
              g_vTh + (size_t)(bh * 64 + r2) * 2048 + (sB >> 1) + i * 8);
    }
    if (tid < 16) cpa16(uM + tid * 16, mask + b * 2048 + tid * 4);
    CP_COMMIT();
    #pragma unroll
    for (int i = 0; i < 4; i++) {
        cpa16(uK + KSTG_B + (uint32_t)(r2 * HSTR) * 2 + sB + i * 16,
              g_kh + (size_t)(bh * 2048 + 64 + r2) * 64 + (sB >> 1) + i * 8);
        cpa16(uV + KSTG_B + (uint32_t)(r2 * HSTR) * 2 + sB + i * 16,
              g_vTh + (size_t)(bh * 64 + r2) * 2048 + 64 + (sB >> 1) + i * 8);
    }
    if (tid < 16) cpa16(uM + 256 + tid * 16, mask + b * 2048 + 64 + tid * 4);
    CP_COMMIT();
    CP_WAIT1();
    __syncthreads();

    // ---- Q fragments: load once, keep in regs for all kt ----
    uint32_t qa[2][4][4];
    #pragma unroll
    for (int mt = 0; mt < 2; mt++) {
        const uint32_t qb = a_addr_h(Qs, qw + (mt << 4), HSTR, lane);
        #pragma unroll
        for (int ks = 0; ks < 4; ks++)
            ldsm4(qa[mt][ks], qb + (ks << 5));
    }

    float acc[16][4] = {};
    float rs[4] = {};

    for (int kt = 0; kt < 32; kt++) {
        const int cur = kt & 1;
        const uint32_t stoff = (uint32_t)cur * KSTG_B;

        // ---- S = Q K^T : 4 k16 steps over dk ----
        float s[16][4] = {};
        #pragma unroll
        for (int ks = 0; ks < 4; ks++) {
            const uint32_t koff = stoff + (uint32_t)(ks << 5);
            #pragma unroll
            for (int j = 0; j < 4; j++) {
                uint32_t bb[4];
                ldsm4(bb, kAdr[j] + koff);
                mma16(s[2 * j],         qa[0][ks], bb);
                mma16(s[2 * j + 1],     qa[0][ks], bb + 2);
                mma16(s[8 + 2 * j],     qa[1][ks], bb);
                mma16(s[8 + 2 * j + 1], qa[1][ks], bb + 2);
            }
        }

        // ---- P = exp(S/8)*mask (fp32 in regs); unrounded row sums ----
        #pragma unroll
        for (int mt = 0; mt < 2; mt++) {
            #pragma unroll
            for (int nt = 0; nt < 8; nt++) {
                const int idx = mt * 8 + nt;
                const float2 mm = *(const float2*)&maskS[cur * 64 + (nt << 3) + (cq << 1)];
                const float p00 = __expf(s[idx][0] * 0.125f) * mm.x;
                const float p01 = __expf(s[idx][1] * 0.125f) * mm.y;
                const float p10 = __expf(s[idx][2] * 0.125f) * mm.x;
                const float p11 = __expf(s[idx][3] * 0.125f) * mm.y;
                rs[mt * 2 + 0] += p00 + p01;
                rs[mt * 2 + 1] += p10 + p11;
                s[idx][0] = p00; s[idx][1] = p01; s[idx][2] = p10; s[idx][3] = p11;
            }
        }

        // ---- acc += P @ V : 4 k16 steps over keys; A = f16x2 packs of s ----
        #pragma unroll
        for (int t = 0; t < 4; t++) {
            const uint32_t koff = stoff + (uint32_t)(t << 5);
            uint32_t a0[4] = { packh(s[2*t][0],   s[2*t][1]),   packh(s[2*t][2],   s[2*t][3]),
                               packh(s[2*t+1][0], s[2*t+1][1]), packh(s[2*t+1][2], s[2*t+1][3]) };
            uint32_t a1[4] = { packh(s[8+2*t][0],   s[8+2*t][1]),   packh(s[8+2*t][2],   s[8+2*t][3]),
                               packh(s[8+2*t+1][0], s[8+2*t+1][1]), packh(s[8+2*t+1][2], s[8+2*t+1][3]) };
            #pragma unroll
            for (int j = 0; j < 4; j++) {
                uint32_t bb[4];
                ldsm4(bb, vAdr[j] + koff);
                mma16(acc[2 * j],         a0, bb);
                mma16(acc[2 * j + 1],     a0, bb + 2);
                mma16(acc[8 + 2 * j],     a1, bb);
                mma16(acc[8 + 2 * j + 1], a1, bb + 2);
            }
        }

        // ---- pipeline: refill this stage with tile kt+2 ----
        __syncthreads();
        if (kt + 2 < 32) {
            const int kn = (kt + 2) << 6;
            #pragma unroll
            for (int i = 0; i < 4; i++) {
                cpa16(uK + stoff + (uint32_t)(r2 * HSTR) * 2 + sB + i * 16,
                      g_kh + (size_t)(bh * 2048 + kn + r2) * 64 + (sB >> 1) + i * 8);
                cpa16(uV + stoff + (uint32_t)(r2 * HSTR) * 2 + sB + i * 16,
                      g_vTh + (size_t)(bh * 64 + r2) * 2048 + kn + (sB >> 1) + i * 8);
            }
            if (tid < 16) cpa16(uM + cur * 256 + tid * 16, mask + b * 2048 + kn + tid * 4);
        }
        CP_COMMIT();
        CP_WAIT1();
        __syncthreads();
    }

    // ---- denominator: reduce across the 4 cq lanes ----
    #pragma unroll
    for (int i = 0; i < 4; i++) {
        rs[i] += __shfl_xor_sync(0xffffffffu, rs[i], 1);
        rs[i] += __shfl_xor_sync(0xffffffffu, rs[i], 2);
        rs[i] = 1.0f / (rs[i] + 1e-8f);
    }

    #pragma unroll
    for (int mt = 0; mt < 2; mt++) {
        const int q_lo = q0 + qw + (mt << 4) + g;
        #pragma unroll
        for (int nt = 0; nt < 8; nt++) {
            const int idx = mt * 8 + nt;
            const int dv = (nt << 3) + (cq << 1);
            *(float2*)&out[(size_t)((b * 2048 + q_lo) * 16 + h) * 64 + dv] =
                make_float2(acc[idx][0] * rs[mt * 2], acc[idx][1] * rs[mt * 2]);
            *(float2*)&out[(size_t)((b * 2048 + q_lo + 8) * 16 + h) * 64 + dv] =
                make_float2(acc[idx][2] * rs[mt * 2 + 1], acc[idx][3] * rs[mt * 2 + 1]);
        }
    }
}

// ---------------------------------------------------------------------------
extern "C" void kernel_launch(void* const* d_in, const int* in_sizes, int n_in,
                              void* d_out, int out_size)
{
    const float* Q    = (const float*)d_in[0];
    const float* mask = (const float*)d_in[1];
    const float* Wq   = (const float*)d_in[2];
    const float* bq   = (const float*)d_in[3];
    const float* Wk   = (const float*)d_in[4];
    const float* bk   = (const float*)d_in[5];
    const float* Wv   = (const float*)d_in[6];
    const float* bv   = (const float*)d_in[7];
    float* out = (float*)d_out;

    cudaFuncSetAttribute(attn_kernel,
                         cudaFuncAttributeMaxDynamicSharedMemorySize, ATTN_SMEM_BYTES);

    round_kernel<<<dim3(4096, 4), 256>>>(Q, Wq, Wk, Wv);
    proj_kernel<<<dim3(8, 32, 3), 256>>>(bq, bk, bv);
    attn_kernel<<<dim3(16, 32), 128, ATTN_SMEM_BYTES>>>(mask, out);
}